// round 3
// baseline (speedup 1.0000x reference)
#include <cuda_runtime.h>
#include <cstdint>
#include <cstddef>

#define N_ 32
#define T_ 2048
#define E_ 512
#define D_ 1024
#define U_ 256

// Scratch (static device globals — no allocation)
__device__ float g_projq[N_ * U_];
__device__ float g_weights[N_ * T_];

// ---------------------------------------------------------------------------
// Kernel 0: proj_q[b,u] = sum_d queries[b,0,d] * W_q[d,u]  (fp64 accumulate)
// ---------------------------------------------------------------------------
__global__ void projq_kernel(const float* __restrict__ q, const float* __restrict__ Wq) {
    int b = blockIdx.x;
    int u = threadIdx.x;  // 256 threads
    __shared__ float qs[D_];
    for (int d = threadIdx.x; d < D_; d += blockDim.x) qs[d] = q[b * D_ + d];
    __syncthreads();
    double acc = 0.0;
#pragma unroll 8
    for (int d = 0; d < D_; ++d) acc = fma((double)qs[d], (double)Wq[d * U_ + u], acc);
    g_projq[b * U_ + u] = (float)acc;
}

// ---------------------------------------------------------------------------
// Kernel 1: fused score GEMM + tanh reduction (exact fp32, f32x2 FFMA)
//   C[r,u] = sum_e mem[r,e]*Wk[e,u];  weights[r] = sum_u v[u]*tanh(C[r,u]+pq[b,u])
// Tile: 32 rows x 256 cols (full U), BK=32. 256 threads: thread = (ty 0..7, tx 0..31)
// owns rows ty*4..+3, cols tx*8..+7, held as 16 packed f32x2 accumulators.
// ---------------------------------------------------------------------------
__global__ __launch_bounds__(256, 2) void score_kernel(
    const float* __restrict__ mem, const float* __restrict__ Wk,
    const float* __restrict__ v) {
    __shared__ float As[32][36];   // [row][k], padded for 16B-aligned f4 stores
    __shared__ float Bs[32][256];  // [k][u]

    int row0 = blockIdx.x * 32;            // global row = b*T + t
    int b = row0 >> 11;                    // row0 / 2048
    int tid = threadIdx.x;
    int tx = tid & 31;                     // lane = column group
    int ty = tid >> 5;                     // warp  = row group

    unsigned long long acc2[4][4];         // [row i][col-pair j]
#pragma unroll
    for (int i = 0; i < 4; i++)
#pragma unroll
        for (int j = 0; j < 4; j++) acc2[i][j] = 0ull;

    const float* A = mem + (size_t)row0 * E_;
    int ar = tid >> 3;                     // A-tile row this thread loads
    int ak = (tid & 7) << 2;               // A-tile k offset (float4)

    for (int k0 = 0; k0 < E_; k0 += 32) {
        float4 a4 = *(const float4*)(A + (size_t)ar * E_ + k0 + ak);
        *(float4*)&As[ar][ak] = a4;
#pragma unroll
        for (int j = 0; j < 8; j++) {
            int i4 = tid + j * 256;
            int kk = i4 >> 6;
            int uu = (i4 & 63) << 2;
            *(float4*)&Bs[kk][uu] = *(const float4*)(Wk + (size_t)(k0 + kk) * U_ + uu);
        }
        __syncthreads();

#pragma unroll
        for (int k = 0; k < 32; k++) {
            unsigned long long a2[4], b2[4];
#pragma unroll
            for (int i = 0; i < 4; i++) {
                unsigned int au = __float_as_uint(As[ty * 4 + i][k]);  // broadcast
                asm("mov.b64 %0, {%1, %1};" : "=l"(a2[i]) : "r"(au));
            }
#pragma unroll
            for (int j = 0; j < 4; j++)
                b2[j] = *(const unsigned long long*)&Bs[k][tx * 8 + j * 2];  // LDS.64
#pragma unroll
            for (int i = 0; i < 4; i++)
#pragma unroll
                for (int j = 0; j < 4; j++)
                    asm("fma.rn.f32x2 %0, %1, %2, %0;"
                        : "+l"(acc2[i][j]) : "l"(a2[i]), "l"(b2[j]));
        }
        __syncthreads();
    }

    // Epilogue: fp64 partial sums of v[u]*tanh(C+pq) over this thread's 8 cols
    double part[4] = {0.0, 0.0, 0.0, 0.0};
#pragma unroll
    for (int j = 0; j < 4; j++) {
        int u0 = tx * 8 + j * 2;
        float pq0 = g_projq[b * U_ + u0];
        float pq1 = g_projq[b * U_ + u0 + 1];
        double v0 = (double)v[u0], v1 = (double)v[u0 + 1];
#pragma unroll
        for (int i = 0; i < 4; i++) {
            unsigned int lo, hi;
            asm("mov.b64 {%0, %1}, %2;" : "=r"(lo), "=r"(hi) : "l"(acc2[i][j]));
            part[i] += v0 * tanh((double)(__uint_as_float(lo) + pq0))
                     + v1 * tanh((double)(__uint_as_float(hi) + pq1));
        }
    }
    // Reduce across warp in double (tx spans all 256 U columns)
#pragma unroll
    for (int off = 16; off > 0; off >>= 1)
#pragma unroll
        for (int i = 0; i < 4; i++)
            part[i] += __shfl_xor_sync(0xffffffffu, part[i], off);
    if (tx == 0) {
#pragma unroll
        for (int i = 0; i < 4; i++) g_weights[row0 + ty * 4 + i] = (float)part[i];
    }
}

// ---------------------------------------------------------------------------
// Kernel 2: per-batch monotonic attention scan over T=2048 — FULL FP64
// one block per batch, 256 threads x 8 elements each, two block prefix scans
// ---------------------------------------------------------------------------
__global__ void scan_kernel(const float* __restrict__ prev, float* __restrict__ out_align) {
    int b = blockIdx.x;
    int tid = threadIdx.x;
    int lane = tid & 31, wid = tid >> 5;
    __shared__ double swarp[8];
    int base = b * T_ + tid * 8;

    double p[8], lpre[8];
    double run = 0.0;
#pragma unroll
    for (int i = 0; i < 8; i++) {
        double w = (double)g_weights[base + i];
        double pi = 1.0 / (1.0 + exp(-w));
        p[i] = pi;
        double omp = fmin(fmax(1.0 - pi, 1e-20), 1.0);
        lpre[i] = run;                 // thread-local exclusive prefix of log(1-p)
        run += log(omp);
    }
    // block exclusive scan of per-thread totals (scan #1)
    double inc = run;
#pragma unroll
    for (int off = 1; off < 32; off <<= 1) {
        double n = __shfl_up_sync(0xffffffffu, inc, off);
        if (lane >= off) inc += n;
    }
    if (lane == 31) swarp[wid] = inc;
    __syncthreads();
    if (tid == 0) {
        double r = 0.0;
        for (int w = 0; w < 8; w++) { double t = swarp[w]; swarp[w] = r; r += t; }
    }
    __syncthreads();
    double texcl = swarp[wid] + (inc - run);  // exclusive log-prefix for this thread
    __syncthreads();

    // second pass: cumprod, s = prev/clip(cumprod), inclusive cumsum of s
    double cp[8], sinc[8];
    double srun = 0.0;
#pragma unroll
    for (int i = 0; i < 8; i++) {
        double c = exp(texcl + lpre[i]);     // exclusive cumprod of (1-p)
        cp[i] = c;
        double cc = fmin(fmax(c, 1e-10), 1.0);
        srun += (double)prev[base + i] / cc;
        sinc[i] = srun;                      // thread-local inclusive prefix
    }
    double inc2 = srun;
#pragma unroll
    for (int off = 1; off < 32; off <<= 1) {
        double n = __shfl_up_sync(0xffffffffu, inc2, off);
        if (lane >= off) inc2 += n;
    }
    if (lane == 31) swarp[wid] = inc2;
    __syncthreads();
    if (tid == 0) {
        double r = 0.0;
        for (int w = 0; w < 8; w++) { double t = swarp[w]; swarp[w] = r; r += t; }
    }
    __syncthreads();
    double sexcl = swarp[wid] + (inc2 - srun);
#pragma unroll
    for (int i = 0; i < 8; i++)
        out_align[base + i] = (float)(p[i] * cp[i] * (sexcl + sinc[i]));
}

// ---------------------------------------------------------------------------
// Kernel 3: contexts[b,e] = sum_t align[b,t]*mem[b,t,e]  (split-T + atomics)
// exact fp32 (error here is ~1e-6, not the amplifier)
// ---------------------------------------------------------------------------
#define T_SPLIT 16
__global__ void ctx_kernel(const float* __restrict__ mem, const float* __restrict__ align,
                           float* __restrict__ ctx) {
    int b = blockIdx.x;
    int chunk = blockIdx.y;
    int e = threadIdx.x;  // 512 threads
    const int TC = T_ / T_SPLIT;
    int t0 = chunk * TC;
    const float* m = mem + ((size_t)b * T_ + t0) * E_ + e;
    const float* a = align + b * T_ + t0;
    float acc = 0.f;
#pragma unroll 4
    for (int t = 0; t < TC; t++)
        acc = fmaf(__ldg(a + t), m[(size_t)t * E_], acc);
    atomicAdd(&ctx[b * E_ + e], acc);
}

// ---------------------------------------------------------------------------
extern "C" void kernel_launch(void* const* d_in, const int* in_sizes, int n_in,
                              void* d_out, int out_size) {
    const float* q    = (const float*)d_in[0];
    const float* prev = (const float*)d_in[1];
    const float* mem  = (const float*)d_in[2];
    const float* Wq   = (const float*)d_in[3];
    const float* Wk   = (const float*)d_in[4];
    const float* v    = (const float*)d_in[5];
    float* out   = (float*)d_out;
    float* ctx   = out;              // [N, E]
    float* align = out + N_ * E_;    // [N, T]

    cudaMemsetAsync(ctx, 0, (size_t)N_ * E_ * sizeof(float));
    projq_kernel<<<N_, 256>>>(q, Wq);
    score_kernel<<<(N_ * T_) / 32, 256>>>(mem, Wk, v);
    scan_kernel<<<N_, 256>>>(prev, align);
    ctx_kernel<<<dim3(N_, T_SPLIT), E_>>>(mem, align, ctx);
}

// round 4
// speedup vs baseline: 2.7650x; 2.7650x over previous
#include <cuda_runtime.h>
#include <cstdint>
#include <cstddef>

#define N_ 32
#define T_ 2048
#define E_ 512
#define D_ 1024
#define U_ 256

// Scratch (static device globals — no allocation)
__device__ __align__(16) float g_projq[N_ * U_];
__device__ __align__(16) float g_weights[N_ * T_];

typedef unsigned long long ull;

__device__ __forceinline__ ull pk2(float lo, float hi) {
    ull r; asm("mov.b64 %0, {%1, %2};" : "=l"(r) : "f"(lo), "f"(hi)); return r;
}
__device__ __forceinline__ ull bc2(float x) {
    ull r; asm("mov.b64 %0, {%1, %1};" : "=l"(r) : "f"(x)); return r;
}
__device__ __forceinline__ void fma2(ull& acc, ull a, ull b) {
    asm("fma.rn.f32x2 %0, %1, %2, %0;" : "+l"(acc) : "l"(a), "l"(b));
}
__device__ __forceinline__ void upk2(ull x, float& lo, float& hi) {
    asm("mov.b64 {%0, %1}, %2;" : "=f"(lo), "=f"(hi) : "l"(x));
}
__device__ __forceinline__ void cpa16(void* dst, const void* src) {
    unsigned d = (unsigned)__cvta_generic_to_shared(dst);
    asm volatile("cp.async.cg.shared.global [%0], [%1], 16;" :: "r"(d), "l"(src));
}

// ---------------------------------------------------------------------------
// Kernel 0: proj_q[b,u] = sum_d queries[b,0,d] * W_q[d,u]  (fp64 accumulate)
// ---------------------------------------------------------------------------
__global__ void projq_kernel(const float* __restrict__ q, const float* __restrict__ Wq) {
    int b = blockIdx.x;
    int u = threadIdx.x;  // 256 threads
    __shared__ float qs[D_];
    for (int d = threadIdx.x; d < D_; d += blockDim.x) qs[d] = q[b * D_ + d];
    __syncthreads();
    double acc = 0.0;
#pragma unroll 8
    for (int d = 0; d < D_; ++d) acc = fma((double)qs[d], (double)Wq[d * U_ + u], acc);
    g_projq[b * U_ + u] = (float)acc;
}

// ---------------------------------------------------------------------------
// Kernel 1: fused score GEMM + tanh reduction (exact fp32, f32x2 FFMA)
// Tile 64 rows x 256 cols, BK=32, 256 threads, 2 CTAs/SM.
// Thread (ty=tid/32, tx=tid%32): rows ty*8..+7, cols {tx*4..+3, 128+tx*4..+3}.
// Accumulators: row-pair packed f32x2, acc[4 row-pairs][8 cols].
// A staged transposed in smem (Ast[k][row], broadcast LDS); B cp.async dbl-buffered.
// ---------------------------------------------------------------------------
#define AST_STRIDE 68              // 64 rows + pad, 16B-aligned row stride (272B)
#define AST_BUF (32 * AST_STRIDE)  // floats per A buffer
#define BS_BUF  (32 * 256)         // floats per B buffer

__global__ __launch_bounds__(256, 2) void score_kernel(
    const float* __restrict__ mem, const float* __restrict__ Wk,
    const float* __restrict__ v) {
    extern __shared__ float sm[];
    float* Ast = sm;                 // [2][32][AST_STRIDE]
    float* Bsm = sm + 2 * AST_BUF;   // [2][32][256]

    const int tid = threadIdx.x;
    const int tx = tid & 31;
    const int ty = tid >> 5;
    const int row0 = blockIdx.x * 64;
    const int b = row0 >> 11;

    const float* Ag = mem + (size_t)row0 * E_;
    const int ar0 = tid >> 3,         ak0 = (tid & 7) << 2;
    const int ar1 = (tid + 256) >> 3, ak1 = ak0;  // same k-offset pattern

    // ---- prologue: tile 0 ----
    float4 a0 = *(const float4*)(Ag + (size_t)ar0 * E_ + ak0);
    float4 a1 = *(const float4*)(Ag + (size_t)ar1 * E_ + ak1);
#pragma unroll
    for (int j = 0; j < 8; j++) {
        int id = tid + (j << 8);
        int kk = id >> 6, uu = (id & 63) << 2;
        cpa16(&Bsm[kk * 256 + uu], Wk + (size_t)kk * U_ + uu);
    }
    asm volatile("cp.async.commit_group;");
    {   // transpose-store A tile 0
        Ast[(ak0 + 0) * AST_STRIDE + ar0] = a0.x;
        Ast[(ak0 + 1) * AST_STRIDE + ar0] = a0.y;
        Ast[(ak0 + 2) * AST_STRIDE + ar0] = a0.z;
        Ast[(ak0 + 3) * AST_STRIDE + ar0] = a0.w;
        Ast[(ak1 + 0) * AST_STRIDE + ar1] = a1.x;
        Ast[(ak1 + 1) * AST_STRIDE + ar1] = a1.y;
        Ast[(ak1 + 2) * AST_STRIDE + ar1] = a1.z;
        Ast[(ak1 + 3) * AST_STRIDE + ar1] = a1.w;
    }

    ull acc[4][8];
#pragma unroll
    for (int i = 0; i < 4; i++)
#pragma unroll
        for (int j = 0; j < 8; j++) acc[i][j] = 0ull;

    int cb = 0;
    for (int it = 0; it < 16; ++it) {
        const int nb = cb ^ 1;
        float4 na0, na1;
        const bool has = (it < 15);
        if (has) {
            const int k0n = (it + 1) << 5;
            na0 = *(const float4*)(Ag + (size_t)ar0 * E_ + k0n + ak0);
            na1 = *(const float4*)(Ag + (size_t)ar1 * E_ + k0n + ak1);
#pragma unroll
            for (int j = 0; j < 8; j++) {
                int id = tid + (j << 8);
                int kk = id >> 6, uu = (id & 63) << 2;
                cpa16(&Bsm[nb * BS_BUF + kk * 256 + uu],
                      Wk + (size_t)(k0n + kk) * U_ + uu);
            }
        }
        asm volatile("cp.async.commit_group;");
        asm volatile("cp.async.wait_group 1;");
        __syncthreads();

        const float* As = Ast + cb * AST_BUF;
        const float* Bs = Bsm + cb * BS_BUF;
#pragma unroll
        for (int k = 0; k < 32; ++k) {
            float4 al = *(const float4*)&As[k * AST_STRIDE + ty * 8];
            float4 ah = *(const float4*)&As[k * AST_STRIDE + ty * 8 + 4];
            float4 b0 = *(const float4*)&Bs[k * 256 + tx * 4];
            float4 b1 = *(const float4*)&Bs[k * 256 + 128 + tx * 4];
            ull ap[4];
            ap[0] = pk2(al.x, al.y); ap[1] = pk2(al.z, al.w);
            ap[2] = pk2(ah.x, ah.y); ap[3] = pk2(ah.z, ah.w);
            ull bp[8];
            bp[0] = bc2(b0.x); bp[1] = bc2(b0.y); bp[2] = bc2(b0.z); bp[3] = bc2(b0.w);
            bp[4] = bc2(b1.x); bp[5] = bc2(b1.y); bp[6] = bc2(b1.z); bp[7] = bc2(b1.w);
#pragma unroll
            for (int r = 0; r < 4; r++)
#pragma unroll
                for (int c = 0; c < 8; c++) fma2(acc[r][c], ap[r], bp[c]);
        }
        __syncthreads();
        if (has) {
            float* An = Ast + nb * AST_BUF;
            An[(ak0 + 0) * AST_STRIDE + ar0] = na0.x;
            An[(ak0 + 1) * AST_STRIDE + ar0] = na0.y;
            An[(ak0 + 2) * AST_STRIDE + ar0] = na0.z;
            An[(ak0 + 3) * AST_STRIDE + ar0] = na0.w;
            An[(ak1 + 0) * AST_STRIDE + ar1] = na1.x;
            An[(ak1 + 1) * AST_STRIDE + ar1] = na1.y;
            An[(ak1 + 2) * AST_STRIDE + ar1] = na1.z;
            An[(ak1 + 3) * AST_STRIDE + ar1] = na1.w;
        }
        cb = nb;
    }

    // ---- epilogue: weights[row] = sum_u v[u]*tanh(C+pq[u]) (fp32) ----
    float4 pqa = *(const float4*)&g_projq[b * U_ + tx * 4];
    float4 pqb = *(const float4*)&g_projq[b * U_ + 128 + tx * 4];
    float4 va  = *(const float4*)&v[tx * 4];
    float4 vb  = *(const float4*)&v[128 + tx * 4];
    float pq[8] = {pqa.x, pqa.y, pqa.z, pqa.w, pqb.x, pqb.y, pqb.z, pqb.w};
    float vv[8] = {va.x, va.y, va.z, va.w, vb.x, vb.y, vb.z, vb.w};

    float rs[8] = {0.f, 0.f, 0.f, 0.f, 0.f, 0.f, 0.f, 0.f};
#pragma unroll
    for (int r = 0; r < 4; r++)
#pragma unroll
        for (int c = 0; c < 8; c++) {
            float lo, hi;
            upk2(acc[r][c], lo, hi);
            rs[2 * r]     += vv[c] * tanhf(lo + pq[c]);
            rs[2 * r + 1] += vv[c] * tanhf(hi + pq[c]);
        }
#pragma unroll
    for (int off = 16; off > 0; off >>= 1)
#pragma unroll
        for (int r = 0; r < 8; r++)
            rs[r] += __shfl_xor_sync(0xffffffffu, rs[r], off);
    if (tx == 0) {
#pragma unroll
        for (int r = 0; r < 8; r++) g_weights[row0 + ty * 8 + r] = rs[r];
    }
}

// ---------------------------------------------------------------------------
// Kernel 2: per-batch monotonic attention scan over T=2048 — FULL FP64
// ---------------------------------------------------------------------------
__global__ void scan_kernel(const float* __restrict__ prev, float* __restrict__ out_align) {
    int b = blockIdx.x;
    int tid = threadIdx.x;
    int lane = tid & 31, wid = tid >> 5;
    __shared__ double swarp[8];
    int base = b * T_ + tid * 8;

    double p[8], lpre[8];
    double run = 0.0;
#pragma unroll
    for (int i = 0; i < 8; i++) {
        double w = (double)g_weights[base + i];
        double pi = 1.0 / (1.0 + exp(-w));
        p[i] = pi;
        double omp = fmin(fmax(1.0 - pi, 1e-20), 1.0);
        lpre[i] = run;
        run += log(omp);
    }
    double inc = run;
#pragma unroll
    for (int off = 1; off < 32; off <<= 1) {
        double n = __shfl_up_sync(0xffffffffu, inc, off);
        if (lane >= off) inc += n;
    }
    if (lane == 31) swarp[wid] = inc;
    __syncthreads();
    if (tid == 0) {
        double r = 0.0;
        for (int w = 0; w < 8; w++) { double t = swarp[w]; swarp[w] = r; r += t; }
    }
    __syncthreads();
    double texcl = swarp[wid] + (inc - run);
    __syncthreads();

    double cp[8], sinc[8];
    double srun = 0.0;
#pragma unroll
    for (int i = 0; i < 8; i++) {
        double c = exp(texcl + lpre[i]);
        cp[i] = c;
        double cc = fmin(fmax(c, 1e-10), 1.0);
        srun += (double)prev[base + i] / cc;
        sinc[i] = srun;
    }
    double inc2 = srun;
#pragma unroll
    for (int off = 1; off < 32; off <<= 1) {
        double n = __shfl_up_sync(0xffffffffu, inc2, off);
        if (lane >= off) inc2 += n;
    }
    if (lane == 31) swarp[wid] = inc2;
    __syncthreads();
    if (tid == 0) {
        double r = 0.0;
        for (int w = 0; w < 8; w++) { double t = swarp[w]; swarp[w] = r; r += t; }
    }
    __syncthreads();
    double sexcl = swarp[wid] + (inc2 - srun);
#pragma unroll
    for (int i = 0; i < 8; i++)
        out_align[base + i] = (float)(p[i] * cp[i] * (sexcl + sinc[i]));
}

// ---------------------------------------------------------------------------
// Kernel 3: contexts[b,e] = sum_t align[b,t]*mem[b,t,e]  (float4, split-T)
// ---------------------------------------------------------------------------
#define T_SPLIT 8
__global__ void ctx_kernel(const float* __restrict__ mem, const float* __restrict__ align,
                           float* __restrict__ ctx) {
    int b = blockIdx.x;
    int chunk = blockIdx.y;
    int tid = threadIdx.x;  // 128 threads, each owns 4 consecutive e
    const int TC = T_ / T_SPLIT;  // 256
    int t0 = chunk * TC;
    const float* m = mem + ((size_t)b * T_ + t0) * E_ + tid * 4;
    const float* a = align + b * T_ + t0;
    float4 acc = {0.f, 0.f, 0.f, 0.f};
#pragma unroll 4
    for (int t = 0; t < TC; t++) {
        float s = __ldg(a + t);
        float4 mv = *(const float4*)(m + (size_t)t * E_);
        acc.x = fmaf(s, mv.x, acc.x);
        acc.y = fmaf(s, mv.y, acc.y);
        acc.z = fmaf(s, mv.z, acc.z);
        acc.w = fmaf(s, mv.w, acc.w);
    }
    float* c = &ctx[b * E_ + tid * 4];
    atomicAdd(c + 0, acc.x);
    atomicAdd(c + 1, acc.y);
    atomicAdd(c + 2, acc.z);
    atomicAdd(c + 3, acc.w);
}

// ---------------------------------------------------------------------------
extern "C" void kernel_launch(void* const* d_in, const int* in_sizes, int n_in,
                              void* d_out, int out_size) {
    const float* q    = (const float*)d_in[0];
    const float* prev = (const float*)d_in[1];
    const float* mem  = (const float*)d_in[2];
    const float* Wq   = (const float*)d_in[3];
    const float* Wk   = (const float*)d_in[4];
    const float* v    = (const float*)d_in[5];
    float* out   = (float*)d_out;
    float* ctx   = out;              // [N, E]
    float* align = out + N_ * E_;    // [N, T]

    const int score_smem = (2 * AST_BUF + 2 * BS_BUF) * sizeof(float);  // 82944 B
    cudaFuncSetAttribute(score_kernel, cudaFuncAttributeMaxDynamicSharedMemorySize,
                         score_smem);

    cudaMemsetAsync(ctx, 0, (size_t)N_ * E_ * sizeof(float));
    projq_kernel<<<N_, 256>>>(q, Wq);
    score_kernel<<<(N_ * T_) / 64, 256, score_smem>>>(mem, Wk, v);
    scan_kernel<<<N_, 256>>>(prev, align);
    ctx_kernel<<<dim3(N_, T_SPLIT), 128>>>(mem, align, ctx);
}

// round 5
// speedup vs baseline: 3.0767x; 1.1128x over previous
#include <cuda_runtime.h>
#include <cstdint>
#include <cstddef>

#define N_ 32
#define T_ 2048
#define E_ 512
#define D_ 1024
#define U_ 256

// Scratch (static device globals — no allocation)
__device__ __align__(16) float g_projq[N_ * U_];
__device__ __align__(16) float g_weights[N_ * T_];
// Pre-split, fragment-permuted B (Wk) for 3xTF32: [kcg 0..63][pair 0..15][lane][reg]
__device__ __align__(16) float g_Bhi[64 * 16 * 32 * 4];
__device__ __align__(16) float g_Blo[64 * 16 * 32 * 4];

__device__ __forceinline__ float tf32r(float x) {
    unsigned int r;
    asm("cvt.rna.tf32.f32 %0, %1;" : "=r"(r) : "f"(x));
    return __uint_as_float(r);
}
__device__ __forceinline__ void cpa16(void* dst, const void* src) {
    unsigned d = (unsigned)__cvta_generic_to_shared(dst);
    asm volatile("cp.async.cg.shared.global [%0], [%1], 16;" :: "r"(d), "l"(src));
}

#define MMA_TF32(dd, aa, b0, b1)                                          \
    asm("mma.sync.aligned.m16n8k8.row.col.f32.tf32.tf32.f32 "             \
        "{%0,%1,%2,%3}, {%4,%5,%6,%7}, {%8,%9}, {%0,%1,%2,%3};"           \
        : "+f"(dd.x), "+f"(dd.y), "+f"(dd.z), "+f"(dd.w)                  \
        : "r"(aa.x), "r"(aa.y), "r"(aa.z), "r"(aa.w), "r"(b0), "r"(b1))

// ---------------------------------------------------------------------------
// B prep: split Wk[k][n] (k=E, n=U) into tf32 hi/lo, permuted to mma fragment
// layout. For (kcg, pair, lane, reg): k = kcg*8 + (lane&3) + ((reg&1)<<2),
// n = pair*16 + ((reg>>1)<<3) + (lane>>2).  32768 (kcg,pair,lane) triples.
// ---------------------------------------------------------------------------
__global__ void bprep_kernel(const float* __restrict__ Wk) {
    int id = blockIdx.x * 256 + threadIdx.x;  // 0..32767
    int lane = id & 31;
    int p = (id >> 5) & 15;
    int kcg = id >> 9;
    float h[4], l[4];
#pragma unroll
    for (int r = 0; r < 4; r++) {
        int k = kcg * 8 + (lane & 3) + ((r & 1) << 2);
        int n = (p << 4) + ((r >> 1) << 3) + (lane >> 2);
        float x = Wk[k * U_ + n];
        float xh = tf32r(x);
        h[r] = xh;
        l[r] = tf32r(x - xh);
    }
    *(float4*)&g_Bhi[id * 4] = make_float4(h[0], h[1], h[2], h[3]);
    *(float4*)&g_Blo[id * 4] = make_float4(l[0], l[1], l[2], l[3]);
}

// ---------------------------------------------------------------------------
// Kernel 0: proj_q[b,u] = sum_d queries[b,0,d] * W_q[d,u]  (fp64 accumulate)
// ---------------------------------------------------------------------------
__global__ void projq_kernel(const float* __restrict__ q, const float* __restrict__ Wq) {
    int b = blockIdx.x;
    int u = threadIdx.x;  // 256 threads
    __shared__ float qs[D_];
    for (int d = threadIdx.x; d < D_; d += blockDim.x) qs[d] = q[b * D_ + d];
    __syncthreads();
    double acc = 0.0;
#pragma unroll 8
    for (int d = 0; d < D_; ++d) acc = fma((double)qs[d], (double)Wq[d * U_ + u], acc);
    g_projq[b * U_ + u] = (float)acc;
}

// ---------------------------------------------------------------------------
// Kernel 1: fused score GEMM via 3xTF32 mma.sync + tanh reduction
// CTA 64 rows x 256 cols, 8 warps (2m x 4n), warp tile 32x64 (2 m16 x 8 n8).
// BK=16 (2 k8-chunks per stage), double-buffered. A split hi/lo at staging;
// B cp.async'd from pre-split fragment-layout g_Bhi/g_Blo.
// Smem (floats): AH[2][1024] | AL[2][1024] | BH[2][4096] | BL[2][4096]
// ---------------------------------------------------------------------------
#define SC_AH(s) ((s) * 1024)
#define SC_AL(s) (2048 + (s) * 1024)
#define SC_BH(s) (4096 + (s) * 4096)
#define SC_BL(s) (12288 + (s) * 4096)
#define SC_SMEM_FLOATS 20480

__device__ __forceinline__ void stage_A(float* sm, int sAH, int sAL, float4 a,
                                        int abase) {
    float x, h;
    x = a.x; h = tf32r(x); sm[sAH + abase + 0] = h;  sm[sAL + abase + 0] = tf32r(x - h);
    x = a.y; h = tf32r(x); sm[sAH + abase + 4] = h;  sm[sAL + abase + 4] = tf32r(x - h);
    x = a.z; h = tf32r(x); sm[sAH + abase + 8] = h;  sm[sAL + abase + 8] = tf32r(x - h);
    x = a.w; h = tf32r(x); sm[sAH + abase + 12] = h; sm[sAL + abase + 12] = tf32r(x - h);
}

__global__ __launch_bounds__(256, 2) void score_kernel(
    const float* __restrict__ mem, const float* __restrict__ v) {
    extern __shared__ float sm[];
    __shared__ float wsum[4][64];

    const int tid = threadIdx.x;
    const int lane = tid & 31;
    const int wid = tid >> 5;
    const int warp_m = wid >> 2;   // 0..1
    const int warp_n = wid & 3;    // 0..3
    const int row0 = blockIdx.x * 64;
    const int b = row0 >> 11;

    // A staging geometry: thread handles row am, k-quarter akq (4 consecutive k)
    const int am = tid >> 2;           // 0..63
    const int akq = tid & 3;           // k0 = akq*4
    const int agmt = am >> 4;          // m16-tile 0..3
    const int ar = am & 15;            // row within m16 tile
    const int akc = akq >> 1;          // k8-chunk 0..1
    const int areg0 = ((akq & 1) ? 2 : 0) + ((ar >= 8) ? 1 : 0);
    // smem float addr for kk-th elem: ((akc*4+agmt)*32 + (ar&7)*4 + kk)*4 + areg0
    const int abase = ((akc * 4 + agmt) * 32 + (ar & 7) * 4) * 4 + areg0;
    const float* Ag = mem + (size_t)(row0 + am) * E_ + akq * 4;

    // ---- prologue: stage 0 ----
    {
        float4 a0 = *(const float4*)Ag;
        stage_A(sm, SC_AH(0), SC_AL(0), a0, abase);
#pragma unroll
        for (int j = 0; j < 4; j++) {
            int fo = (tid + j * 256) * 4;
            cpa16(&sm[SC_BH(0) + fo], g_Bhi + fo);
            cpa16(&sm[SC_BL(0) + fo], g_Blo + fo);
        }
        asm volatile("cp.async.commit_group;");
    }

    float4 d[2][8];
#pragma unroll
    for (int mt = 0; mt < 2; mt++)
#pragma unroll
        for (int nt = 0; nt < 8; nt++) d[mt][nt] = make_float4(0.f, 0.f, 0.f, 0.f);

    int cb = 0;
    for (int it = 0; it < 32; ++it) {
        const int nb = cb ^ 1;
        const bool has = (it < 31);
        float4 an;
        if (has) {
            an = *(const float4*)(Ag + (it + 1) * 16);
            const int goff = (it + 1) * 4096;
#pragma unroll
            for (int j = 0; j < 4; j++) {
                int fo = (tid + j * 256) * 4;
                cpa16(&sm[SC_BH(nb) + fo], g_Bhi + goff + fo);
                cpa16(&sm[SC_BL(nb) + fo], g_Blo + goff + fo);
            }
        }
        asm volatile("cp.async.commit_group;");
        asm volatile("cp.async.wait_group 1;");
        __syncthreads();

        const float* AH = sm + SC_AH(cb);
        const float* AL = sm + SC_AL(cb);
        const float* BH = sm + SC_BH(cb);
        const float* BL = sm + SC_BL(cb);
#pragma unroll
        for (int kc = 0; kc < 2; kc++) {
            uint4 ah[2], al[2];
#pragma unroll
            for (int mt = 0; mt < 2; mt++) {
                int gmt = warp_m * 2 + mt;
                int ai = ((kc * 4 + gmt) * 32 + lane) * 4;
                ah[mt] = *(const uint4*)&AH[ai];
                al[mt] = *(const uint4*)&AL[ai];
            }
#pragma unroll
            for (int ntp = 0; ntp < 4; ntp++) {
                int p = warp_n * 4 + ntp;
                int bi = ((kc * 16 + p) * 32 + lane) * 4;
                uint4 bh = *(const uint4*)&BH[bi];
                uint4 bl = *(const uint4*)&BL[bi];
#pragma unroll
                for (int mt = 0; mt < 2; mt++) {
                    // small terms first, then the main hi*hi term
                    MMA_TF32(d[mt][ntp * 2],     al[mt], bh.x, bh.y);
                    MMA_TF32(d[mt][ntp * 2],     ah[mt], bl.x, bl.y);
                    MMA_TF32(d[mt][ntp * 2],     ah[mt], bh.x, bh.y);
                    MMA_TF32(d[mt][ntp * 2 + 1], al[mt], bh.z, bh.w);
                    MMA_TF32(d[mt][ntp * 2 + 1], ah[mt], bl.z, bl.w);
                    MMA_TF32(d[mt][ntp * 2 + 1], ah[mt], bh.z, bh.w);
                }
            }
        }
        __syncthreads();
        if (has) stage_A(sm, SC_AH(nb), SC_AL(nb), an, abase);
        cb = nb;
    }

    // ---- epilogue: weights[row] = sum_u v[u]*tanh(C+pq[u]) ----
    float rsum[2][2] = {{0.f, 0.f}, {0.f, 0.f}};  // [mt][row / row+8]
#pragma unroll
    for (int nt = 0; nt < 8; nt++) {
        int c0 = warp_n * 64 + nt * 8 + (lane & 3) * 2;
        float v0 = v[c0], v1 = v[c0 + 1];
        float pq0 = g_projq[b * U_ + c0], pq1 = g_projq[b * U_ + c0 + 1];
#pragma unroll
        for (int mt = 0; mt < 2; mt++) {
            float4 dd = d[mt][nt];
            rsum[mt][0] += v0 * tanhf(dd.x + pq0) + v1 * tanhf(dd.y + pq1);
            rsum[mt][1] += v0 * tanhf(dd.z + pq0) + v1 * tanhf(dd.w + pq1);
        }
    }
#pragma unroll
    for (int off = 1; off <= 2; off <<= 1)
#pragma unroll
        for (int mt = 0; mt < 2; mt++)
#pragma unroll
            for (int j = 0; j < 2; j++)
                rsum[mt][j] += __shfl_xor_sync(0xffffffffu, rsum[mt][j], off);
    if ((lane & 3) == 0) {
#pragma unroll
        for (int mt = 0; mt < 2; mt++)
#pragma unroll
            for (int j = 0; j < 2; j++)
                wsum[warp_n][warp_m * 32 + mt * 16 + j * 8 + (lane >> 2)] = rsum[mt][j];
    }
    __syncthreads();
    if (tid < 64)
        g_weights[row0 + tid] =
            wsum[0][tid] + wsum[1][tid] + wsum[2][tid] + wsum[3][tid];
}

// ---------------------------------------------------------------------------
// Kernel 2: per-batch monotonic attention scan over T=2048 — FULL FP64
// ---------------------------------------------------------------------------
__global__ void scan_kernel(const float* __restrict__ prev, float* __restrict__ out_align) {
    int b = blockIdx.x;
    int tid = threadIdx.x;
    int lane = tid & 31, wid = tid >> 5;
    __shared__ double swarp[8];
    int base = b * T_ + tid * 8;

    double p[8], lpre[8];
    double run = 0.0;
#pragma unroll
    for (int i = 0; i < 8; i++) {
        double w = (double)g_weights[base + i];
        double pi = 1.0 / (1.0 + exp(-w));
        p[i] = pi;
        double omp = fmin(fmax(1.0 - pi, 1e-20), 1.0);
        lpre[i] = run;
        run += log(omp);
    }
    double inc = run;
#pragma unroll
    for (int off = 1; off < 32; off <<= 1) {
        double n = __shfl_up_sync(0xffffffffu, inc, off);
        if (lane >= off) inc += n;
    }
    if (lane == 31) swarp[wid] = inc;
    __syncthreads();
    if (tid == 0) {
        double r = 0.0;
        for (int w = 0; w < 8; w++) { double t = swarp[w]; swarp[w] = r; r += t; }
    }
    __syncthreads();
    double texcl = swarp[wid] + (inc - run);
    __syncthreads();

    double cp[8], sinc[8];
    double srun = 0.0;
#pragma unroll
    for (int i = 0; i < 8; i++) {
        double c = exp(texcl + lpre[i]);
        cp[i] = c;
        double cc = fmin(fmax(c, 1e-10), 1.0);
        srun += (double)prev[base + i] / cc;
        sinc[i] = srun;
    }
    double inc2 = srun;
#pragma unroll
    for (int off = 1; off < 32; off <<= 1) {
        double n = __shfl_up_sync(0xffffffffu, inc2, off);
        if (lane >= off) inc2 += n;
    }
    if (lane == 31) swarp[wid] = inc2;
    __syncthreads();
    if (tid == 0) {
        double r = 0.0;
        for (int w = 0; w < 8; w++) { double t = swarp[w]; swarp[w] = r; r += t; }
    }
    __syncthreads();
    double sexcl = swarp[wid] + (inc2 - srun);
#pragma unroll
    for (int i = 0; i < 8; i++)
        out_align[base + i] = (float)(p[i] * cp[i] * (sexcl + sinc[i]));
}

// ---------------------------------------------------------------------------
// Kernel 3: contexts[b,e] = sum_t align[b,t]*mem[b,t,e]
// grid (N, 32) x 256 threads, float2 per thread — high occupancy + MLP
// ---------------------------------------------------------------------------
#define CT_SPLIT 32
__global__ void ctx_kernel(const float* __restrict__ mem, const float* __restrict__ align,
                           float* __restrict__ ctx) {
    int b = blockIdx.x;
    int chunk = blockIdx.y;
    int tid = threadIdx.x;  // 256 threads, each owns 2 consecutive e
    const int TC = T_ / CT_SPLIT;  // 64
    int t0 = chunk * TC;
    const float* m = mem + ((size_t)b * T_ + t0) * E_ + tid * 2;
    const float* a = align + b * T_ + t0;
    float ax = 0.f, ay = 0.f;
#pragma unroll 4
    for (int t = 0; t < TC; t++) {
        float s = __ldg(a + t);
        float2 mv = *(const float2*)(m + (size_t)t * E_);
        ax = fmaf(s, mv.x, ax);
        ay = fmaf(s, mv.y, ay);
    }
    float* c = &ctx[b * E_ + tid * 2];
    atomicAdd(c + 0, ax);
    atomicAdd(c + 1, ay);
}

// ---------------------------------------------------------------------------
extern "C" void kernel_launch(void* const* d_in, const int* in_sizes, int n_in,
                              void* d_out, int out_size) {
    const float* q    = (const float*)d_in[0];
    const float* prev = (const float*)d_in[1];
    const float* mem  = (const float*)d_in[2];
    const float* Wq   = (const float*)d_in[3];
    const float* Wk   = (const float*)d_in[4];
    const float* v    = (const float*)d_in[5];
    float* out   = (float*)d_out;
    float* ctx   = out;              // [N, E]
    float* align = out + N_ * E_;    // [N, T]

    const int score_smem = SC_SMEM_FLOATS * sizeof(float);  // 81920 B
    cudaFuncSetAttribute(score_kernel, cudaFuncAttributeMaxDynamicSharedMemorySize,
                         score_smem);

    cudaMemsetAsync(ctx, 0, (size_t)N_ * E_ * sizeof(float));
    bprep_kernel<<<128, 256>>>(Wk);
    projq_kernel<<<N_, 256>>>(q, Wq);
    score_kernel<<<(N_ * T_) / 64, 256, score_smem>>>(mem, v);
    scan_kernel<<<N_, 256>>>(prev, align);
    ctx_kernel<<<dim3(N_, CT_SPLIT), 256>>>(mem, align, ctx);
}

// round 7
// speedup vs baseline: 3.1797x; 1.0335x over previous
#include <cuda_runtime.h>
#include <cstdint>
#include <cstddef>

#define N_ 32
#define T_ 2048
#define E_ 512
#define D_ 1024
#define U_ 256

// Scratch (static device globals — no allocation)
__device__ __align__(16) float g_projq[N_ * U_];
__device__ __align__(16) float g_weights[N_ * T_];
// Pre-split, fragment-permuted B (Wk) for 3xTF32: [kcg 0..63][pair 0..15][lane][reg]
__device__ __align__(16) float g_Bhi[64 * 16 * 32 * 4];
__device__ __align__(16) float g_Blo[64 * 16 * 32 * 4];
// fp64 scan intermediates
__device__ __align__(16) double g_pD[N_ * T_];
__device__ __align__(16) double g_lD[N_ * T_];
__device__ __align__(16) double g_texcl[N_ * T_];
__device__ __align__(16) double g_sD[N_ * T_];
__device__ __align__(16) double g_acp[N_ * T_];

__device__ __forceinline__ float tf32r(float x) {
    unsigned int r;
    asm("cvt.rna.tf32.f32 %0, %1;" : "=r"(r) : "f"(x));
    return __uint_as_float(r);
}
__device__ __forceinline__ void cpa16(void* dst, const void* src) {
    unsigned d = (unsigned)__cvta_generic_to_shared(dst);
    asm volatile("cp.async.cg.shared.global [%0], [%1], 16;" :: "r"(d), "l"(src));
}

#define MMA_TF32(dd, aa, b0, b1)                                          \
    asm("mma.sync.aligned.m16n8k8.row.col.f32.tf32.tf32.f32 "             \
        "{%0,%1,%2,%3}, {%4,%5,%6,%7}, {%8,%9}, {%0,%1,%2,%3};"           \
        : "+f"(dd.x), "+f"(dd.y), "+f"(dd.z), "+f"(dd.w)                  \
        : "r"(aa.x), "r"(aa.y), "r"(aa.z), "r"(aa.w), "r"(b0), "r"(b1))

// ---------------------------------------------------------------------------
// B prep: split Wk[k][n] into tf32 hi/lo, permuted to mma fragment layout.
// ---------------------------------------------------------------------------
__global__ void bprep_kernel(const float* __restrict__ Wk) {
    int id = blockIdx.x * 256 + threadIdx.x;  // 0..32767
    int lane = id & 31;
    int p = (id >> 5) & 15;
    int kcg = id >> 9;
    float h[4], l[4];
#pragma unroll
    for (int r = 0; r < 4; r++) {
        int k = kcg * 8 + (lane & 3) + ((r & 1) << 2);
        int n = (p << 4) + ((r >> 1) << 3) + (lane >> 2);
        float x = Wk[k * U_ + n];
        float xh = tf32r(x);
        h[r] = xh;
        l[r] = tf32r(x - xh);
    }
    *(float4*)&g_Bhi[id * 4] = make_float4(h[0], h[1], h[2], h[3]);
    *(float4*)&g_Blo[id * 4] = make_float4(l[0], l[1], l[2], l[3]);
}

// ---------------------------------------------------------------------------
// proj_q (fp64 accumulate)
// ---------------------------------------------------------------------------
__global__ void projq_kernel(const float* __restrict__ q, const float* __restrict__ Wq) {
    int b = blockIdx.x;
    int u = threadIdx.x;
    __shared__ float qs[D_];
    for (int d = threadIdx.x; d < D_; d += blockDim.x) qs[d] = q[b * D_ + d];
    __syncthreads();
    double acc = 0.0;
#pragma unroll 8
    for (int d = 0; d < D_; ++d) acc = fma((double)qs[d], (double)Wq[d * U_ + u], acc);
    g_projq[b * U_ + u] = (float)acc;
}

// ---------------------------------------------------------------------------
// Kernel 1: fused score GEMM via 3xTF32 mma.sync, TERM-MAJOR ordering.
// CTA 64x256, 8 warps (2m x 4n), warp tile 32x64. BK=16 double-buffered.
// ---------------------------------------------------------------------------
#define SC_AH(s) ((s) * 1024)
#define SC_AL(s) (2048 + (s) * 1024)
#define SC_BH(s) (4096 + (s) * 4096)
#define SC_BL(s) (12288 + (s) * 4096)
#define SC_SMEM_FLOATS 20480

__device__ __forceinline__ void stage_A(float* sm, int sAH, int sAL, float4 a,
                                        int abase) {
    float x, h;
    x = a.x; h = tf32r(x); sm[sAH + abase + 0] = h;  sm[sAL + abase + 0] = tf32r(x - h);
    x = a.y; h = tf32r(x); sm[sAH + abase + 4] = h;  sm[sAL + abase + 4] = tf32r(x - h);
    x = a.z; h = tf32r(x); sm[sAH + abase + 8] = h;  sm[sAL + abase + 8] = tf32r(x - h);
    x = a.w; h = tf32r(x); sm[sAH + abase + 12] = h; sm[sAL + abase + 12] = tf32r(x - h);
}

__global__ __launch_bounds__(256, 2) void score_kernel(
    const float* __restrict__ mem, const float* __restrict__ v) {
    extern __shared__ float sm[];
    __shared__ float wsum[4][64];

    const int tid = threadIdx.x;
    const int lane = tid & 31;
    const int wid = tid >> 5;
    const int warp_m = wid >> 2;   // 0..1
    const int warp_n = wid & 3;    // 0..3
    const int row0 = blockIdx.x * 64;
    const int b = row0 >> 11;

    const int am = tid >> 2;
    const int akq = tid & 3;
    const int agmt = am >> 4;
    const int ar = am & 15;
    const int akc = akq >> 1;
    const int areg0 = ((akq & 1) ? 2 : 0) + ((ar >= 8) ? 1 : 0);
    const int abase = ((akc * 4 + agmt) * 32 + (ar & 7) * 4) * 4 + areg0;
    const float* Ag = mem + (size_t)(row0 + am) * E_ + akq * 4;

    // ---- prologue: stage 0 ----
    {
        float4 a0 = *(const float4*)Ag;
        stage_A(sm, SC_AH(0), SC_AL(0), a0, abase);
#pragma unroll
        for (int j = 0; j < 4; j++) {
            int fo = (tid + j * 256) * 4;
            cpa16(&sm[SC_BH(0) + fo], g_Bhi + fo);
            cpa16(&sm[SC_BL(0) + fo], g_Blo + fo);
        }
        asm volatile("cp.async.commit_group;");
    }

    float4 d[2][8];
#pragma unroll
    for (int mt = 0; mt < 2; mt++)
#pragma unroll
        for (int nt = 0; nt < 8; nt++) d[mt][nt] = make_float4(0.f, 0.f, 0.f, 0.f);

    int cb = 0;
    for (int it = 0; it < 32; ++it) {
        const int nb = cb ^ 1;
        const bool has = (it < 31);
        float4 an;
        if (has) {
            an = *(const float4*)(Ag + (it + 1) * 16);
            const int goff = (it + 1) * 4096;
#pragma unroll
            for (int j = 0; j < 4; j++) {
                int fo = (tid + j * 256) * 4;
                cpa16(&sm[SC_BH(nb) + fo], g_Bhi + goff + fo);
                cpa16(&sm[SC_BL(nb) + fo], g_Blo + goff + fo);
            }
        }
        asm volatile("cp.async.commit_group;");
        asm volatile("cp.async.wait_group 1;");
        __syncthreads();

        const float* AH = sm + SC_AH(cb);
        const float* AL = sm + SC_AL(cb);
        const float* BH = sm + SC_BH(cb);
        const float* BL = sm + SC_BL(cb);
#pragma unroll
        for (int kc = 0; kc < 2; kc++) {
            // load ALL fragments for this k8-chunk first
            uint4 ah[2], al[2], bh[4], bl[4];
#pragma unroll
            for (int mt = 0; mt < 2; mt++) {
                int gmt = warp_m * 2 + mt;
                int ai = ((kc * 4 + gmt) * 32 + lane) * 4;
                ah[mt] = *(const uint4*)&AH[ai];
                al[mt] = *(const uint4*)&AL[ai];
            }
#pragma unroll
            for (int p = 0; p < 4; p++) {
                int bi = ((kc * 16 + warp_n * 4 + p) * 32 + lane) * 4;
                bh[p] = *(const uint4*)&BH[bi];
                bl[p] = *(const uint4*)&BL[bi];
            }
            // term-major: 3 passes x 16 independent accumulators
            // pass 1: al x bh
#pragma unroll
            for (int p = 0; p < 4; p++)
#pragma unroll
                for (int mt = 0; mt < 2; mt++) {
                    MMA_TF32(d[mt][p * 2],     al[mt], bh[p].x, bh[p].y);
                    MMA_TF32(d[mt][p * 2 + 1], al[mt], bh[p].z, bh[p].w);
                }
            // pass 2: ah x bl
#pragma unroll
            for (int p = 0; p < 4; p++)
#pragma unroll
                for (int mt = 0; mt < 2; mt++) {
                    MMA_TF32(d[mt][p * 2],     ah[mt], bl[p].x, bl[p].y);
                    MMA_TF32(d[mt][p * 2 + 1], ah[mt], bl[p].z, bl[p].w);
                }
            // pass 3: ah x bh (main term)
#pragma unroll
            for (int p = 0; p < 4; p++)
#pragma unroll
                for (int mt = 0; mt < 2; mt++) {
                    MMA_TF32(d[mt][p * 2],     ah[mt], bh[p].x, bh[p].y);
                    MMA_TF32(d[mt][p * 2 + 1], ah[mt], bh[p].z, bh[p].w);
                }
        }
        __syncthreads();
        if (has) stage_A(sm, SC_AH(nb), SC_AL(nb), an, abase);
        cb = nb;
    }

    // ---- epilogue: weights[row] = sum_u v[u]*tanh(C+pq[u]) ----
    float rsum[2][2] = {{0.f, 0.f}, {0.f, 0.f}};
#pragma unroll
    for (int nt = 0; nt < 8; nt++) {
        int c0 = warp_n * 64 + nt * 8 + (lane & 3) * 2;
        float v0 = v[c0], v1 = v[c0 + 1];
        float pq0 = g_projq[b * U_ + c0], pq1 = g_projq[b * U_ + c0 + 1];
#pragma unroll
        for (int mt = 0; mt < 2; mt++) {
            float4 dd = d[mt][nt];
            rsum[mt][0] += v0 * tanhf(dd.x + pq0) + v1 * tanhf(dd.y + pq1);
            rsum[mt][1] += v0 * tanhf(dd.z + pq0) + v1 * tanhf(dd.w + pq1);
        }
    }
#pragma unroll
    for (int off = 1; off <= 2; off <<= 1)
#pragma unroll
        for (int mt = 0; mt < 2; mt++)
#pragma unroll
            for (int j = 0; j < 2; j++)
                rsum[mt][j] += __shfl_xor_sync(0xffffffffu, rsum[mt][j], off);
    if ((lane & 3) == 0) {
#pragma unroll
        for (int mt = 0; mt < 2; mt++)
#pragma unroll
            for (int j = 0; j < 2; j++)
                wsum[warp_n][warp_m * 32 + mt * 16 + j * 8 + (lane >> 2)] = rsum[mt][j];
    }
    __syncthreads();
    if (tid < 64)
        g_weights[row0 + tid] =
            wsum[0][tid] + wsum[1][tid] + wsum[2][tid] + wsum[3][tid];
}

// ---------------------------------------------------------------------------
// S1: parallel fp64 transcendentals: p = sigmoid(w), l = log(clip(1-p))
// ---------------------------------------------------------------------------
__global__ void scan1_kernel() {
    int i = blockIdx.x * 256 + threadIdx.x;
    double w = (double)g_weights[i];
    double p = 1.0 / (1.0 + exp(-w));
    double omp = fmin(fmax(1.0 - p, 1e-20), 1.0);
    g_pD[i] = p;
    g_lD[i] = log(omp);
}

// ---------------------------------------------------------------------------
// S2: per-batch exclusive cumsum of l -> texcl (pure fp64 adds)
// ---------------------------------------------------------------------------
__global__ void scan2_kernel() {
    int b = blockIdx.x;
    int tid = threadIdx.x;
    int lane = tid & 31, wid = tid >> 5;
    __shared__ double swarp[8];
    int base = b * T_ + tid * 8;
    double x[8], run = 0.0;
#pragma unroll
    for (int i = 0; i < 8; i++) {
        x[i] = run;
        run += g_lD[base + i];
    }
    double inc = run;
#pragma unroll
    for (int off = 1; off < 32; off <<= 1) {
        double n = __shfl_up_sync(0xffffffffu, inc, off);
        if (lane >= off) inc += n;
    }
    if (lane == 31) swarp[wid] = inc;
    __syncthreads();
    if (tid == 0) {
        double r = 0.0;
        for (int w = 0; w < 8; w++) { double t = swarp[w]; swarp[w] = r; r += t; }
    }
    __syncthreads();
    double texcl = swarp[wid] + (inc - run);
#pragma unroll
    for (int i = 0; i < 8; i++) g_texcl[base + i] = texcl + x[i];
}

// ---------------------------------------------------------------------------
// S3: parallel fp64: cp = exp(texcl); s = prev/clip(cp); acp = p*cp
// ---------------------------------------------------------------------------
__global__ void scan3_kernel(const float* __restrict__ prev) {
    int i = blockIdx.x * 256 + threadIdx.x;
    double cp = exp(g_texcl[i]);
    double cc = fmin(fmax(cp, 1e-10), 1.0);
    g_sD[i] = (double)prev[i] / cc;
    g_acp[i] = g_pD[i] * cp;
}

// ---------------------------------------------------------------------------
// S4: per-batch inclusive cumsum of s; align = acp * cumsum
// ---------------------------------------------------------------------------
__global__ void scan4_kernel(float* __restrict__ out_align) {
    int b = blockIdx.x;
    int tid = threadIdx.x;
    int lane = tid & 31, wid = tid >> 5;
    __shared__ double swarp[8];
    int base = b * T_ + tid * 8;
    double sinc[8], run = 0.0;
#pragma unroll
    for (int i = 0; i < 8; i++) {
        run += g_sD[base + i];
        sinc[i] = run;
    }
    double inc = run;
#pragma unroll
    for (int off = 1; off < 32; off <<= 1) {
        double n = __shfl_up_sync(0xffffffffu, inc, off);
        if (lane >= off) inc += n;
    }
    if (lane == 31) swarp[wid] = inc;
    __syncthreads();
    if (tid == 0) {
        double r = 0.0;
        for (int w = 0; w < 8; w++) { double t = swarp[w]; swarp[w] = r; r += t; }
    }
    __syncthreads();
    double sexcl = swarp[wid] + (inc - run);
#pragma unroll
    for (int i = 0; i < 8; i++)
        out_align[base + i] = (float)(g_acp[base + i] * (sexcl + sinc[i]));
}

// ---------------------------------------------------------------------------
// contexts[b,e] = sum_t align[b,t]*mem[b,t,e]
// ---------------------------------------------------------------------------
#define CT_SPLIT 32
__global__ void ctx_kernel(const float* __restrict__ mem, const float* __restrict__ align,
                           float* __restrict__ ctx) {
    int b = blockIdx.x;
    int chunk = blockIdx.y;
    int tid = threadIdx.x;
    const int TC = T_ / CT_SPLIT;
    int t0 = chunk * TC;
    const float* m = mem + ((size_t)b * T_ + t0) * E_ + tid * 2;
    const float* a = align + b * T_ + t0;
    float ax = 0.f, ay = 0.f;
#pragma unroll 4
    for (int t = 0; t < TC; t++) {
        float s = __ldg(a + t);
        float2 mv = *(const float2*)(m + (size_t)t * E_);
        ax = fmaf(s, mv.x, ax);
        ay = fmaf(s, mv.y, ay);
    }
    float* c = &ctx[b * E_ + tid * 2];
    atomicAdd(c + 0, ax);
    atomicAdd(c + 1, ay);
}

// ---------------------------------------------------------------------------
extern "C" void kernel_launch(void* const* d_in, const int* in_sizes, int n_in,
                              void* d_out, int out_size) {
    const float* q    = (const float*)d_in[0];
    const float* prev = (const float*)d_in[1];
    const float* mem  = (const float*)d_in[2];
    const float* Wq   = (const float*)d_in[3];
    const float* Wk   = (const float*)d_in[4];
    const float* v    = (const float*)d_in[5];
    float* out   = (float*)d_out;
    float* ctx   = out;              // [N, E]
    float* align = out + N_ * E_;    // [N, T]

    const int score_smem = SC_SMEM_FLOATS * sizeof(float);  // 81920 B
    cudaFuncSetAttribute(score_kernel, cudaFuncAttributeMaxDynamicSharedMemorySize,
                         score_smem);

    cudaMemsetAsync(ctx, 0, (size_t)N_ * E_ * sizeof(float));
    bprep_kernel<<<128, 256>>>(Wk);
    projq_kernel<<<N_, 256>>>(q, Wq);
    score_kernel<<<(N_ * T_) / 64, 256, score_smem>>>(mem, v);
    scan1_kernel<<<256, 256>>>();
    scan2_kernel<<<N_, 256>>>();
    scan3_kernel<<<256, 256>>>(prev);
    scan4_kernel<<<N_, 256>>>(align);
    ctx_kernel<<<dim3(N_, CT_SPLIT), 256>>>(mem, align, ctx);
}

// round 8
// speedup vs baseline: 3.9859x; 1.2535x over previous
#include <cuda_runtime.h>
#include <cuda_fp16.h>
#include <cstdint>
#include <cstddef>

#define N_ 32
#define T_ 2048
#define E_ 512
#define D_ 1024
#define U_ 256

// Scratch (static device globals — no allocation)
__device__ __align__(16) float g_projq[N_ * U_];
__device__ __align__(16) float g_wpart[2][N_ * T_];
// Pre-split fragment-layout B (Wk): [c 0..31][p 0..15][lane 0..31][4 words(half2)]
__device__ __align__(16) unsigned int g_Bh[32 * 16 * 32 * 4];
__device__ __align__(16) unsigned int g_Bm[32 * 16 * 32 * 4];
// fp64 scan intermediates
__device__ __align__(16) double g_pD[N_ * T_];
__device__ __align__(16) double g_lD[N_ * T_];
__device__ __align__(16) double g_texcl[N_ * T_];
__device__ __align__(16) double g_sD[N_ * T_];
__device__ __align__(16) double g_acp[N_ * T_];

__device__ __forceinline__ void cpa16(void* dst, const void* src) {
    unsigned d = (unsigned)__cvta_generic_to_shared(dst);
    asm volatile("cp.async.cg.shared.global [%0], [%1], 16;" :: "r"(d), "l"(src));
}
__device__ __forceinline__ unsigned int packh2(float x0, float x1) {
    __half2 h = __floats2half2_rn(x0, x1);
    return *(unsigned int*)&h;
}
// split x into fp16 hi + fp16 mid (Markidis)
__device__ __forceinline__ void spl2(float x, __half& h, __half& m) {
    h = __float2half_rn(x);
    m = __float2half_rn(x - __half2float(h));
}

#define MMA_F16(dd, aa, b0, b1)                                           \
    asm("mma.sync.aligned.m16n8k16.row.col.f32.f16.f16.f32 "              \
        "{%0,%1,%2,%3}, {%4,%5,%6,%7}, {%8,%9}, {%0,%1,%2,%3};"           \
        : "+f"(dd.x), "+f"(dd.y), "+f"(dd.z), "+f"(dd.w)                  \
        : "r"(aa.x), "r"(aa.y), "r"(aa.z), "r"(aa.w), "r"(b0), "r"(b1))

// ---------------------------------------------------------------------------
// B prep: split Wk[k][n] into fp16 hi/mid, permuted into m16n8k16 B-fragment
// layout. Word w of (c,p,lane): nblk = 2p+(w>>1), reg = w&1,
// n = nblk*8 + (lane>>2), k = c*16 + (lane&3)*2 + reg*8 + {0,1}.
// ---------------------------------------------------------------------------
__global__ void bprep_kernel(const float* __restrict__ Wk) {
    int id = blockIdx.x * 256 + threadIdx.x;  // 0..16383
    int lane = id & 31;
    int p = (id >> 5) & 15;
    int c = id >> 9;
    unsigned int hw[4], mw[4];
#pragma unroll
    for (int w = 0; w < 4; w++) {
        int nblk = p * 2 + (w >> 1);
        int reg = w & 1;
        int n = nblk * 8 + (lane >> 2);
        int k0 = c * 16 + (lane & 3) * 2 + reg * 8;
        float x0 = Wk[k0 * U_ + n];
        float x1 = Wk[(k0 + 1) * U_ + n];
        __half h0, m0, h1, m1;
        spl2(x0, h0, m0);
        spl2(x1, h1, m1);
        hw[w] = ((unsigned int)__half_as_ushort(h1) << 16) | __half_as_ushort(h0);
        mw[w] = ((unsigned int)__half_as_ushort(m1) << 16) | __half_as_ushort(m0);
    }
    *(uint4*)&g_Bh[id * 4] = make_uint4(hw[0], hw[1], hw[2], hw[3]);
    *(uint4*)&g_Bm[id * 4] = make_uint4(mw[0], mw[1], mw[2], mw[3]);
}

// ---------------------------------------------------------------------------
// proj_q (fp64 accumulate)
// ---------------------------------------------------------------------------
__global__ void projq_kernel(const float* __restrict__ q, const float* __restrict__ Wq) {
    int b = blockIdx.x;
    int u = threadIdx.x;
    __shared__ float qs[D_];
    for (int d = threadIdx.x; d < D_; d += blockDim.x) qs[d] = q[b * D_ + d];
    __syncthreads();
    double acc = 0.0;
#pragma unroll 8
    for (int d = 0; d < D_; ++d) acc = fma((double)qs[d], (double)Wq[d * U_ + u], acc);
    g_projq[b * U_ + u] = (float)acc;
}

// ---------------------------------------------------------------------------
// Score GEMM: fp16 2-way split, 3 terms (hh, am*bh, ah*bm), m16n8k16.
// CTA = 64 rows x 128 cols (blockIdx.y = col half). 8 warps: warp_m 0..1 (32
// rows), warp_n 0..3 (32 cols = 4 n8-blocks = 2 pairs). BK=16 dbl-buffered.
// Smem bytes/stage: AH 2048 | AM 2048 | BH 4096 | BM 4096 = 12288; x2 = 24576.
// ---------------------------------------------------------------------------
#define ST_AH 0
#define ST_AM 2048
#define ST_BH 4096
#define ST_BM 8192
#define ST_STRIDE 12288
#define SC_SMEM (2 * ST_STRIDE)

__device__ __forceinline__ void stage_A(char* stg, float4 a, int am, int kq) {
    int tile = am >> 4;
    int rbit = ((am & 15) >= 8) ? 1 : 0;
    int j0 = kq * 2;
#pragma unroll
    for (int jj = 0; jj < 2; jj++) {
        int j = j0 + jj;
        int lane = (am & 7) * 4 + (j & 3);
        int reg = ((j >= 4) ? 2 : 0) + rbit;
        float x0 = jj ? a.z : a.x;
        float x1 = jj ? a.w : a.y;
        __half h0, m0, h1, m1;
        spl2(x0, h0, m0);
        spl2(x1, h1, m1);
        unsigned off = ((tile * 32 + lane) * 4 + reg) * 4;
        *(unsigned int*)(stg + ST_AH + off) =
            ((unsigned int)__half_as_ushort(h1) << 16) | __half_as_ushort(h0);
        *(unsigned int*)(stg + ST_AM + off) =
            ((unsigned int)__half_as_ushort(m1) << 16) | __half_as_ushort(m0);
    }
}

__global__ __launch_bounds__(256, 2) void score_kernel(
    const float* __restrict__ mem, const float* __restrict__ v) {
    extern __shared__ char smem[];
    __shared__ float wsum[4][64];

    const int tid = threadIdx.x;
    const int lane = tid & 31;
    const int wid = tid >> 5;
    const int warp_m = wid >> 2;   // 0..1
    const int warp_n = wid & 3;    // 0..3
    const int row0 = blockIdx.x * 64;
    const int cb = blockIdx.y;     // col half 0..1
    const int b = row0 >> 11;

    const int am = tid >> 2;       // A row this thread stages
    const int kq = tid & 3;        // k quartet
    const float* Ag = mem + (size_t)(row0 + am) * E_ + kq * 4;

    // global B source offset for this CTA's col half, per chunk: 8 p-entries
    const unsigned bsrc_stride = 16 * 32 * 4;  // words per chunk
    const unsigned bsrc_cb = (unsigned)(cb * 8 * 32 * 4);

    // ---- prologue: stage 0 ----
    {
        float4 a0 = *(const float4*)Ag;
        stage_A(smem, a0, am, kq);
        const unsigned so = bsrc_cb + tid * 4;
        cpa16(smem + ST_BH + tid * 16, g_Bh + so);
        cpa16(smem + ST_BM + tid * 16, g_Bm + so);
        asm volatile("cp.async.commit_group;");
    }

    float4 d[2][4];
#pragma unroll
    for (int mt = 0; mt < 2; mt++)
#pragma unroll
        for (int nt = 0; nt < 4; nt++) d[mt][nt] = make_float4(0.f, 0.f, 0.f, 0.f);

    int cbuf = 0;
    for (int it = 0; it < 32; ++it) {
        const int nbuf = cbuf ^ 1;
        const bool has = (it < 31);
        float4 an;
        if (has) {
            an = *(const float4*)(Ag + (it + 1) * 16);
            const unsigned so = (it + 1) * bsrc_stride + bsrc_cb + tid * 4;
            cpa16(smem + nbuf * ST_STRIDE + ST_BH + tid * 16, g_Bh + so);
            cpa16(smem + nbuf * ST_STRIDE + ST_BM + tid * 16, g_Bm + so);
        }
        asm volatile("cp.async.commit_group;");
        asm volatile("cp.async.wait_group 1;");
        __syncthreads();

        char* stg = smem + cbuf * ST_STRIDE;
        // load fragments
        uint4 ah[2], amf[2], bhv[2], bmv[2];
#pragma unroll
        for (int mt = 0; mt < 2; mt++) {
            unsigned off = (((warp_m * 2 + mt) * 32 + lane) * 4) * 4;
            ah[mt] = *(const uint4*)(stg + ST_AH + off);
            amf[mt] = *(const uint4*)(stg + ST_AM + off);
        }
#pragma unroll
        for (int q = 0; q < 2; q++) {
            unsigned off = (((warp_n * 2 + q) * 32 + lane) * 4) * 4;
            bhv[q] = *(const uint4*)(stg + ST_BH + off);
            bmv[q] = *(const uint4*)(stg + ST_BM + off);
        }
        // term-major: 3 passes x 8 independent accumulators
#pragma unroll
        for (int q = 0; q < 2; q++)
#pragma unroll
            for (int mt = 0; mt < 2; mt++) {
                MMA_F16(d[mt][q * 2],     amf[mt], bhv[q].x, bhv[q].y);
                MMA_F16(d[mt][q * 2 + 1], amf[mt], bhv[q].z, bhv[q].w);
            }
#pragma unroll
        for (int q = 0; q < 2; q++)
#pragma unroll
            for (int mt = 0; mt < 2; mt++) {
                MMA_F16(d[mt][q * 2],     ah[mt], bmv[q].x, bmv[q].y);
                MMA_F16(d[mt][q * 2 + 1], ah[mt], bmv[q].z, bmv[q].w);
            }
#pragma unroll
        for (int q = 0; q < 2; q++)
#pragma unroll
            for (int mt = 0; mt < 2; mt++) {
                MMA_F16(d[mt][q * 2],     ah[mt], bhv[q].x, bhv[q].y);
                MMA_F16(d[mt][q * 2 + 1], ah[mt], bhv[q].z, bhv[q].w);
            }
        __syncthreads();
        if (has) stage_A(smem + nbuf * ST_STRIDE, an, am, kq);
        cbuf = nbuf;
    }

    // ---- epilogue: partial weights over this CTA's 128 cols ----
    float rsum[2][2] = {{0.f, 0.f}, {0.f, 0.f}};
#pragma unroll
    for (int nt = 0; nt < 4; nt++) {
        int c0 = cb * 128 + warp_n * 32 + nt * 8 + (lane & 3) * 2;
        float v0 = v[c0], v1 = v[c0 + 1];
        float pq0 = g_projq[b * U_ + c0], pq1 = g_projq[b * U_ + c0 + 1];
#pragma unroll
        for (int mt = 0; mt < 2; mt++) {
            float4 dd = d[mt][nt];
            rsum[mt][0] += v0 * tanhf(dd.x + pq0) + v1 * tanhf(dd.y + pq1);
            rsum[mt][1] += v0 * tanhf(dd.z + pq0) + v1 * tanhf(dd.w + pq1);
        }
    }
#pragma unroll
    for (int off = 1; off <= 2; off <<= 1)
#pragma unroll
        for (int mt = 0; mt < 2; mt++)
#pragma unroll
            for (int j = 0; j < 2; j++)
                rsum[mt][j] += __shfl_xor_sync(0xffffffffu, rsum[mt][j], off);
    if ((lane & 3) == 0) {
#pragma unroll
        for (int mt = 0; mt < 2; mt++)
#pragma unroll
            for (int j = 0; j < 2; j++)
                wsum[warp_n][warp_m * 32 + mt * 16 + j * 8 + (lane >> 2)] = rsum[mt][j];
    }
    __syncthreads();
    if (tid < 64)
        g_wpart[cb][row0 + tid] =
            wsum[0][tid] + wsum[1][tid] + wsum[2][tid] + wsum[3][tid];
}

// ---------------------------------------------------------------------------
// S1: parallel fp64 transcendentals: p = sigmoid(w), l = log(clip(1-p))
// ---------------------------------------------------------------------------
__global__ void scan1_kernel() {
    int i = blockIdx.x * 256 + threadIdx.x;
    double w = (double)g_wpart[0][i] + (double)g_wpart[1][i];
    double p = 1.0 / (1.0 + exp(-w));
    double omp = fmin(fmax(1.0 - p, 1e-20), 1.0);
    g_pD[i] = p;
    g_lD[i] = log(omp);
}

// ---------------------------------------------------------------------------
// S2: per-batch exclusive cumsum of l -> texcl
// ---------------------------------------------------------------------------
__global__ void scan2_kernel() {
    int b = blockIdx.x;
    int tid = threadIdx.x;
    int lane = tid & 31, wid = tid >> 5;
    __shared__ double swarp[8];
    int base = b * T_ + tid * 8;
    double x[8], run = 0.0;
#pragma unroll
    for (int i = 0; i < 8; i++) {
        x[i] = run;
        run += g_lD[base + i];
    }
    double inc = run;
#pragma unroll
    for (int off = 1; off < 32; off <<= 1) {
        double n = __shfl_up_sync(0xffffffffu, inc, off);
        if (lane >= off) inc += n;
    }
    if (lane == 31) swarp[wid] = inc;
    __syncthreads();
    if (tid == 0) {
        double r = 0.0;
        for (int w = 0; w < 8; w++) { double t = swarp[w]; swarp[w] = r; r += t; }
    }
    __syncthreads();
    double texcl = swarp[wid] + (inc - run);
#pragma unroll
    for (int i = 0; i < 8; i++) g_texcl[base + i] = texcl + x[i];
}

// ---------------------------------------------------------------------------
// S3: parallel fp64: cp = exp(texcl); s = prev/clip(cp); acp = p*cp
// ---------------------------------------------------------------------------
__global__ void scan3_kernel(const float* __restrict__ prev) {
    int i = blockIdx.x * 256 + threadIdx.x;
    double cp = exp(g_texcl[i]);
    double cc = fmin(fmax(cp, 1e-10), 1.0);
    g_sD[i] = (double)prev[i] / cc;
    g_acp[i] = g_pD[i] * cp;
}

// ---------------------------------------------------------------------------
// S4: per-batch inclusive cumsum of s; align = acp * cumsum
// ---------------------------------------------------------------------------
__global__ void scan4_kernel(float* __restrict__ out_align) {
    int b = blockIdx.x;
    int tid = threadIdx.x;
    int lane = tid & 31, wid = tid >> 5;
    __shared__ double swarp[8];
    int base = b * T_ + tid * 8;
    double sinc[8], run = 0.0;
#pragma unroll
    for (int i = 0; i < 8; i++) {
        run += g_sD[base + i];
        sinc[i] = run;
    }
    double inc = run;
#pragma unroll
    for (int off = 1; off < 32; off <<= 1) {
        double n = __shfl_up_sync(0xffffffffu, inc, off);
        if (lane >= off) inc += n;
    }
    if (lane == 31) swarp[wid] = inc;
    __syncthreads();
    if (tid == 0) {
        double r = 0.0;
        for (int w = 0; w < 8; w++) { double t = swarp[w]; swarp[w] = r; r += t; }
    }
    __syncthreads();
    double sexcl = swarp[wid] + (inc - run);
#pragma unroll
    for (int i = 0; i < 8; i++)
        out_align[base + i] = (float)(g_acp[base + i] * (sexcl + sinc[i]));
}

// ---------------------------------------------------------------------------
// contexts[b,e] = sum_t align[b,t]*mem[b,t,e]   (512 thr, 1024 blocks)
// ---------------------------------------------------------------------------
#define CT_SPLIT 32
__global__ void ctx_kernel(const float* __restrict__ mem, const float* __restrict__ align,
                           float* __restrict__ ctx) {
    int b = blockIdx.x;
    int chunk = blockIdx.y;
    int e = threadIdx.x;  // 512 threads
    const int TC = T_ / CT_SPLIT;  // 64
    int t0 = chunk * TC;
    const float* m = mem + ((size_t)b * T_ + t0) * E_ + e;
    const float* a = align + b * T_ + t0;
    float acc = 0.f;
#pragma unroll 8
    for (int t = 0; t < TC; t++)
        acc = fmaf(__ldg(a + t), m[(size_t)t * E_], acc);
    atomicAdd(&ctx[b * E_ + e], acc);
}

// ---------------------------------------------------------------------------
extern "C" void kernel_launch(void* const* d_in, const int* in_sizes, int n_in,
                              void* d_out, int out_size) {
    const float* q    = (const float*)d_in[0];
    const float* prev = (const float*)d_in[1];
    const float* mem  = (const float*)d_in[2];
    const float* Wq   = (const float*)d_in[3];
    const float* Wk   = (const float*)d_in[4];
    const float* v    = (const float*)d_in[5];
    float* out   = (float*)d_out;
    float* ctx   = out;              // [N, E]
    float* align = out + N_ * E_;    // [N, T]

    cudaMemsetAsync(ctx, 0, (size_t)N_ * E_ * sizeof(float));
    bprep_kernel<<<64, 256>>>(Wk);
    projq_kernel<<<N_, 256>>>(q, Wq);
    score_kernel<<<dim3((N_ * T_) / 64, 2), 256, SC_SMEM>>>(mem, v);
    scan1_kernel<<<256, 256>>>();
    scan2_kernel<<<N_, 256>>>();
    scan3_kernel<<<256, 256>>>(prev);
    scan4_kernel<<<N_, 256>>>(align);
    ctx_kernel<<<dim3(N_, CT_SPLIT), 512>>>(mem, align, ctx);
}

// round 10
// speedup vs baseline: 4.0038x; 1.0045x over previous
#include <cuda_runtime.h>
#include <cuda_fp16.h>
#include <cstdint>
#include <cstddef>

#define N_ 32
#define T_ 2048
#define E_ 512
#define D_ 1024
#define U_ 256

// Scratch (static device globals — no allocation)
__device__ __align__(16) float g_projq[N_ * U_];
__device__ __align__(16) float g_wpart[2][N_ * T_];
// Pre-split fragment-layout B (Wk): [c 0..31][p 0..15][lane 0..31][4 words(half2)]
__device__ __align__(16) unsigned int g_Bh[32 * 16 * 32 * 4];
__device__ __align__(16) unsigned int g_Bm[32 * 16 * 32 * 4];
// fp64 scan intermediates
__device__ __align__(16) double g_pD[N_ * T_];
__device__ __align__(16) double g_lD[N_ * T_];
__device__ __align__(16) double g_texcl[N_ * T_];
__device__ __align__(16) double g_sD[N_ * T_];
__device__ __align__(16) double g_acp[N_ * T_];

__device__ __forceinline__ void cpa16(void* dst, const void* src) {
    unsigned d = (unsigned)__cvta_generic_to_shared(dst);
    asm volatile("cp.async.cg.shared.global [%0], [%1], 16;" :: "r"(d), "l"(src));
}
// split x into fp16 hi + fp16 mid (Markidis)
__device__ __forceinline__ void spl2(float x, __half& h, __half& m) {
    h = __float2half_rn(x);
    m = __float2half_rn(x - __half2float(h));
}

#define MMA_F16(dd, aa, b0, b1)                                           \
    asm("mma.sync.aligned.m16n8k16.row.col.f32.f16.f16.f32 "              \
        "{%0,%1,%2,%3}, {%4,%5,%6,%7}, {%8,%9}, {%0,%1,%2,%3};"           \
        : "+f"(dd.x), "+f"(dd.y), "+f"(dd.z), "+f"(dd.w)                  \
        : "r"(aa.x), "r"(aa.y), "r"(aa.z), "r"(aa.w), "r"(b0), "r"(b1))

// ---------------------------------------------------------------------------
// B prep: split Wk[k][n] into fp16 hi/mid, permuted into m16n8k16 B-fragment
// layout. Word w of (c,p,lane): nblk = 2p+(w>>1), reg = w&1,
// n = nblk*8 + (lane>>2), k = c*16 + (lane&3)*2 + reg*8 + {0,1}.
// ---------------------------------------------------------------------------
__global__ void bprep_kernel(const float* __restrict__ Wk) {
    int id = blockIdx.x * 256 + threadIdx.x;  // 0..16383
    int lane = id & 31;
    int p = (id >> 5) & 15;
    int c = id >> 9;
    unsigned int hw[4], mw[4];
#pragma unroll
    for (int w = 0; w < 4; w++) {
        int nblk = p * 2 + (w >> 1);
        int reg = w & 1;
        int n = nblk * 8 + (lane >> 2);
        int k0 = c * 16 + (lane & 3) * 2 + reg * 8;
        float x0 = Wk[k0 * U_ + n];
        float x1 = Wk[(k0 + 1) * U_ + n];
        __half h0, m0, h1, m1;
        spl2(x0, h0, m0);
        spl2(x1, h1, m1);
        hw[w] = ((unsigned int)__half_as_ushort(h1) << 16) | __half_as_ushort(h0);
        mw[w] = ((unsigned int)__half_as_ushort(m1) << 16) | __half_as_ushort(m0);
    }
    *(uint4*)&g_Bh[id * 4] = make_uint4(hw[0], hw[1], hw[2], hw[3]);
    *(uint4*)&g_Bm[id * 4] = make_uint4(mw[0], mw[1], mw[2], mw[3]);
}

// ---------------------------------------------------------------------------
// proj_q (fp64 accumulate)
// ---------------------------------------------------------------------------
__global__ void projq_kernel(const float* __restrict__ q, const float* __restrict__ Wq) {
    int b = blockIdx.x;
    int u = threadIdx.x;
    __shared__ float qs[D_];
    for (int d = threadIdx.x; d < D_; d += blockDim.x) qs[d] = q[b * D_ + d];
    __syncthreads();
    double acc = 0.0;
#pragma unroll 8
    for (int d = 0; d < D_; ++d) acc = fma((double)qs[d], (double)Wq[d * U_ + u], acc);
    g_projq[b * U_ + u] = (float)acc;
}

// ---------------------------------------------------------------------------
// No-op kernel: aligns score_kernel to the ncu-profiled launch slot (#4).
// ---------------------------------------------------------------------------
__global__ void align_prof_kernel() {}

// ---------------------------------------------------------------------------
// Score GEMM: fp16 2-way split, 3 terms (hh, am*bh, ah*bm), m16n8k16.
// CTA = 64 rows x 128 cols (blockIdx.y = col half). 8 warps: warp_m 0..1,
// warp_n 0..3. BK=32 (2 k16-chunks per stage), double-buffered.
// Smem/stage: AH 4KB | AM 4KB | BH 8KB | BM 8KB = 24KB; x2 = 48KB dynamic.
// ---------------------------------------------------------------------------
#define ST_AH 0
#define ST_AM 4096
#define ST_BH 8192
#define ST_BM 16384
#define ST_STRIDE 24576
#define SC_SMEM (2 * ST_STRIDE)

__device__ __forceinline__ void stage_A(char* stg, float4 a, int am, int kq, int kc) {
    int tile = am >> 4;
    int rbit = ((am & 15) >= 8) ? 1 : 0;
#pragma unroll
    for (int jj = 0; jj < 2; jj++) {
        int j = kq * 2 + jj;
        int lane = (am & 7) * 4 + (j & 3);
        int reg = ((j >= 4) ? 2 : 0) + rbit;
        float x0 = jj ? a.z : a.x;
        float x1 = jj ? a.w : a.y;
        __half h0, m0, h1, m1;
        spl2(x0, h0, m0);
        spl2(x1, h1, m1);
        unsigned off = (((kc * 4 + tile) * 32 + lane) * 4 + reg) * 4;
        *(unsigned int*)(stg + ST_AH + off) =
            ((unsigned int)__half_as_ushort(h1) << 16) | __half_as_ushort(h0);
        *(unsigned int*)(stg + ST_AM + off) =
            ((unsigned int)__half_as_ushort(m1) << 16) | __half_as_ushort(m0);
    }
}

__global__ __launch_bounds__(256, 2) void score_kernel(
    const float* __restrict__ mem, const float* __restrict__ v) {
    extern __shared__ char smem[];
    __shared__ float wsum[4][64];

    const int tid = threadIdx.x;
    const int lane = tid & 31;
    const int wid = tid >> 5;
    const int warp_m = wid >> 2;   // 0..1
    const int warp_n = wid & 3;    // 0..3
    const int row0 = blockIdx.x * 64;
    const int cb = blockIdx.y;     // col half 0..1
    const int b = row0 >> 11;

    const int am = tid >> 2;       // A row this thread stages
    const int kq = tid & 3;        // k quartet within a k16 chunk
    const float* Ag = mem + (size_t)(row0 + am) * E_ + kq * 4;

    const unsigned bsrc_c = 16 * 32 * 4;            // words per k16 chunk (2048)
    const unsigned bsrc_cb = (unsigned)(cb * 8 * 32 * 4);  // 1024-word half

    // ---- prologue: stage chunk-pair 0 into buffer 0 ----
    {
        float4 a0 = *(const float4*)Ag;
        float4 a1 = *(const float4*)(Ag + 16);
        stage_A(smem, a0, am, kq, 0);
        stage_A(smem, a1, am, kq, 1);
#pragma unroll
        for (int kc = 0; kc < 2; kc++) {
            const unsigned so = kc * bsrc_c + bsrc_cb + tid * 4;
            cpa16(smem + ST_BH + (kc * 1024 + tid * 4) * 4, g_Bh + so);
            cpa16(smem + ST_BM + (kc * 1024 + tid * 4) * 4, g_Bm + so);
        }
        asm volatile("cp.async.commit_group;");
    }

    float4 d[2][4];
#pragma unroll
    for (int mt = 0; mt < 2; mt++)
#pragma unroll
        for (int nt = 0; nt < 4; nt++) d[mt][nt] = make_float4(0.f, 0.f, 0.f, 0.f);

    int cbuf = 0;
    for (int it = 0; it < 16; ++it) {
        const int nbuf = cbuf ^ 1;
        const bool has = (it < 15);
        float4 an0, an1;
        if (has) {
            an0 = *(const float4*)(Ag + (it + 1) * 32);
            an1 = *(const float4*)(Ag + (it + 1) * 32 + 16);
#pragma unroll
            for (int kc = 0; kc < 2; kc++) {
                const unsigned so = (2 * (it + 1) + kc) * bsrc_c + bsrc_cb + tid * 4;
                cpa16(smem + nbuf * ST_STRIDE + ST_BH + (kc * 1024 + tid * 4) * 4,
                      g_Bh + so);
                cpa16(smem + nbuf * ST_STRIDE + ST_BM + (kc * 1024 + tid * 4) * 4,
                      g_Bm + so);
            }
        }
        asm volatile("cp.async.commit_group;");
        asm volatile("cp.async.wait_group 1;");
        __syncthreads();

        char* stg = smem + cbuf * ST_STRIDE;
#pragma unroll
        for (int kc = 0; kc < 2; kc++) {
            uint4 ah[2], amf[2], bhv[2], bmv[2];
#pragma unroll
            for (int mt = 0; mt < 2; mt++) {
                unsigned off = (((kc * 4 + warp_m * 2 + mt) * 32 + lane) * 4) * 4;
                ah[mt] = *(const uint4*)(stg + ST_AH + off);
                amf[mt] = *(const uint4*)(stg + ST_AM + off);
            }
#pragma unroll
            for (int q = 0; q < 2; q++) {
                unsigned off = ((kc * 8 + warp_n * 2 + q) * 128 + lane * 4) * 4;
                bhv[q] = *(const uint4*)(stg + ST_BH + off);
                bmv[q] = *(const uint4*)(stg + ST_BM + off);
            }
            // term-major: 3 passes x 8 independent accumulators
#pragma unroll
            for (int q = 0; q < 2; q++)
#pragma unroll
                for (int mt = 0; mt < 2; mt++) {
                    MMA_F16(d[mt][q * 2],     amf[mt], bhv[q].x, bhv[q].y);
                    MMA_F16(d[mt][q * 2 + 1], amf[mt], bhv[q].z, bhv[q].w);
                }
#pragma unroll
            for (int q = 0; q < 2; q++)
#pragma unroll
                for (int mt = 0; mt < 2; mt++) {
                    MMA_F16(d[mt][q * 2],     ah[mt], bmv[q].x, bmv[q].y);
                    MMA_F16(d[mt][q * 2 + 1], ah[mt], bmv[q].z, bmv[q].w);
                }
#pragma unroll
            for (int q = 0; q < 2; q++)
#pragma unroll
                for (int mt = 0; mt < 2; mt++) {
                    MMA_F16(d[mt][q * 2],     ah[mt], bhv[q].x, bhv[q].y);
                    MMA_F16(d[mt][q * 2 + 1], ah[mt], bhv[q].z, bhv[q].w);
                }
        }
        __syncthreads();
        if (has) {
            char* nstg = smem + nbuf * ST_STRIDE;
            stage_A(nstg, an0, am, kq, 0);
            stage_A(nstg, an1, am, kq, 1);
        }
        cbuf = nbuf;
    }

    // ---- epilogue: partial weights over this CTA's 128 cols ----
    float rsum[2][2] = {{0.f, 0.f}, {0.f, 0.f}};
#pragma unroll
    for (int nt = 0; nt < 4; nt++) {
        int c0 = cb * 128 + warp_n * 32 + nt * 8 + (lane & 3) * 2;
        float v0 = v[c0], v1 = v[c0 + 1];
        float pq0 = g_projq[b * U_ + c0], pq1 = g_projq[b * U_ + c0 + 1];
#pragma unroll
        for (int mt = 0; mt < 2; mt++) {
            float4 dd = d[mt][nt];
            rsum[mt][0] += v0 * tanhf(dd.x + pq0) + v1 * tanhf(dd.y + pq1);
            rsum[mt][1] += v0 * tanhf(dd.z + pq0) + v1 * tanhf(dd.w + pq1);
        }
    }
#pragma unroll
    for (int off = 1; off <= 2; off <<= 1)
#pragma unroll
        for (int mt = 0; mt < 2; mt++)
#pragma unroll
            for (int j = 0; j < 2; j++)
                rsum[mt][j] += __shfl_xor_sync(0xffffffffu, rsum[mt][j], off);
    if ((lane & 3) == 0) {
#pragma unroll
        for (int mt = 0; mt < 2; mt++)
#pragma unroll
            for (int j = 0; j < 2; j++)
                wsum[warp_n][warp_m * 32 + mt * 16 + j * 8 + (lane >> 2)] = rsum[mt][j];
    }
    __syncthreads();
    if (tid < 64)
        g_wpart[cb][row0 + tid] =
            wsum[0][tid] + wsum[1][tid] + wsum[2][tid] + wsum[3][tid];
}

// ---------------------------------------------------------------------------
// S1: parallel fp64 transcendentals: p = sigmoid(w), l = log(clip(1-p))
// ---------------------------------------------------------------------------
__global__ void scan1_kernel() {
    int i = blockIdx.x * 256 + threadIdx.x;
    double w = (double)g_wpart[0][i] + (double)g_wpart[1][i];
    double p = 1.0 / (1.0 + exp(-w));
    double omp = fmin(fmax(1.0 - p, 1e-20), 1.0);
    g_pD[i] = p;
    g_lD[i] = log(omp);
}

// ---------------------------------------------------------------------------
// S2: per-batch exclusive cumsum of l -> texcl
// ---------------------------------------------------------------------------
__global__ void scan2_kernel() {
    int b = blockIdx.x;
    int tid = threadIdx.x;
    int lane = tid & 31, wid = tid >> 5;
    __shared__ double swarp[8];
    int base = b * T_ + tid * 8;
    double x[8], run = 0.0;
#pragma unroll
    for (int i = 0; i < 8; i++) {
        x[i] = run;
        run += g_lD[base + i];
    }
    double inc = run;
#pragma unroll
    for (int off = 1; off < 32; off <<= 1) {
        double n = __shfl_up_sync(0xffffffffu, inc, off);
        if (lane >= off) inc += n;
    }
    if (lane == 31) swarp[wid] = inc;
    __syncthreads();
    if (tid == 0) {
        double r = 0.0;
        for (int w = 0; w < 8; w++) { double t = swarp[w]; swarp[w] = r; r += t; }
    }
    __syncthreads();
    double texcl = swarp[wid] + (inc - run);
#pragma unroll
    for (int i = 0; i < 8; i++) g_texcl[base + i] = texcl + x[i];
}

// ---------------------------------------------------------------------------
// S3: parallel fp64: cp = exp(texcl); s = prev/clip(cp); acp = p*cp
// ---------------------------------------------------------------------------
__global__ void scan3_kernel(const float* __restrict__ prev) {
    int i = blockIdx.x * 256 + threadIdx.x;
    double cp = exp(g_texcl[i]);
    double cc = fmin(fmax(cp, 1e-10), 1.0);
    g_sD[i] = (double)prev[i] / cc;
    g_acp[i] = g_pD[i] * cp;
}

// ---------------------------------------------------------------------------
// S4: per-batch inclusive cumsum of s; align = acp * cumsum
// ---------------------------------------------------------------------------
__global__ void scan4_kernel(float* __restrict__ out_align) {
    int b = blockIdx.x;
    int tid = threadIdx.x;
    int lane = tid & 31, wid = tid >> 5;
    __shared__ double swarp[8];
    int base = b * T_ + tid * 8;
    double sinc[8], run = 0.0;
#pragma unroll
    for (int i = 0; i < 8; i++) {
        run += g_sD[base + i];
        sinc[i] = run;
    }
    double inc = run;
#pragma unroll
    for (int off = 1; off < 32; off <<= 1) {
        double n = __shfl_up_sync(0xffffffffu, inc, off);
        if (lane >= off) inc += n;
    }
    if (lane == 31) swarp[wid] = inc;
    __syncthreads();
    if (tid == 0) {
        double r = 0.0;
        for (int w = 0; w < 8; w++) { double t = swarp[w]; swarp[w] = r; r += t; }
    }
    __syncthreads();
    double sexcl = swarp[wid] + (inc - run);
#pragma unroll
    for (int i = 0; i < 8; i++)
        out_align[base + i] = (float)(g_acp[base + i] * (sexcl + sinc[i]));
}

// ---------------------------------------------------------------------------
// contexts[b,e] = sum_t align[b,t]*mem[b,t,e]   (512 thr, 1024 blocks)
// ---------------------------------------------------------------------------
#define CT_SPLIT 32
__global__ void ctx_kernel(const float* __restrict__ mem, const float* __restrict__ align,
                           float* __restrict__ ctx) {
    int b = blockIdx.x;
    int chunk = blockIdx.y;
    int e = threadIdx.x;  // 512 threads
    const int TC = T_ / CT_SPLIT;  // 64
    int t0 = chunk * TC;
    const float* m = mem + ((size_t)b * T_ + t0) * E_ + e;
    const float* a = align + b * T_ + t0;
    float acc = 0.f;
#pragma unroll 8
    for (int t = 0; t < TC; t++)
        acc = fmaf(__ldg(a + t), m[(size_t)t * E_], acc);
    atomicAdd(&ctx[b * E_ + e], acc);
}

// ---------------------------------------------------------------------------
extern "C" void kernel_launch(void* const* d_in, const int* in_sizes, int n_in,
                              void* d_out, int out_size) {
    const float* q    = (const float*)d_in[0];
    const float* prev = (const float*)d_in[1];
    const float* mem  = (const float*)d_in[2];
    const float* Wq   = (const float*)d_in[3];
    const float* Wk   = (const float*)d_in[4];
    const float* v    = (const float*)d_in[5];
    float* out   = (float*)d_out;
    float* ctx   = out;              // [N, E]
    float* align = out + N_ * E_;    // [N, T]

    // 48KB dynamic smem + 1KB static needs the opt-in (dropped in R7 — that
    // missing call is what broke R9's launch/capture).
    cudaFuncSetAttribute(score_kernel, cudaFuncAttributeMaxDynamicSharedMemorySize,
                         SC_SMEM);

    cudaMemsetAsync(ctx, 0, (size_t)N_ * E_ * sizeof(float));
    bprep_kernel<<<64, 256>>>(Wk);
    projq_kernel<<<N_, 256>>>(q, Wq);
    align_prof_kernel<<<1, 32>>>();   // slot #3 — makes score the profiled launch
    score_kernel<<<dim3((N_ * T_) / 64, 2), 256, SC_SMEM>>>(mem, v);
    scan1_kernel<<<256, 256>>>();
    scan2_kernel<<<N_, 256>>>();
    scan3_kernel<<<256, 256>>>(prev);
    scan4_kernel<<<N_, 256>>>(align);
    ctx_kernel<<<dim3(N_, CT_SPLIT), 512>>>(mem, align, ctx);
}

// round 11
// speedup vs baseline: 6.0868x; 1.5202x over previous
#include <cuda_runtime.h>
#include <cuda_fp16.h>
#include <cstdint>
#include <cstddef>

#define N_ 32
#define T_ 2048
#define E_ 512
#define D_ 1024
#define U_ 256

// Scratch (static device globals — no allocation)
__device__ __align__(16) float g_pqpart[4][N_ * U_];
__device__ __align__(16) float g_wpart[2][N_ * T_];
// Pre-split fragment-layout B (Wk): [c 0..31][p 0..15][lane 0..31][4 words(half2)]
__device__ __align__(16) unsigned int g_Bh[32 * 16 * 32 * 4];
__device__ __align__(16) unsigned int g_Bm[32 * 16 * 32 * 4];
// fp64 scan intermediates
__device__ __align__(16) double g_pD[N_ * T_];
__device__ __align__(16) double g_lD[N_ * T_];
__device__ __align__(16) double g_texcl[N_ * T_];

__device__ __forceinline__ void cpa16(void* dst, const void* src) {
    unsigned d = (unsigned)__cvta_generic_to_shared(dst);
    asm volatile("cp.async.cg.shared.global [%0], [%1], 16;" :: "r"(d), "l"(src));
}
// split x into fp16 hi + fp16 mid (Markidis)
__device__ __forceinline__ void spl2(float x, __half& h, __half& m) {
    h = __float2half_rn(x);
    m = __float2half_rn(x - __half2float(h));
}

#define MMA_F16(dd, aa, b0, b1)                                           \
    asm("mma.sync.aligned.m16n8k16.row.col.f32.f16.f16.f32 "              \
        "{%0,%1,%2,%3}, {%4,%5,%6,%7}, {%8,%9}, {%0,%1,%2,%3};"           \
        : "+f"(dd.x), "+f"(dd.y), "+f"(dd.z), "+f"(dd.w)                  \
        : "r"(aa.x), "r"(aa.y), "r"(aa.z), "r"(aa.w), "r"(b0), "r"(b1))

// ---------------------------------------------------------------------------
// B prep: split Wk[k][n] into fp16 hi/mid, permuted into m16n8k16 B-fragment
// layout. Word w of (c,p,lane): nblk = 2p+(w>>1), reg = w&1,
// n = nblk*8 + (lane>>2), k = c*16 + (lane&3)*2 + reg*8 + {0,1}.
// ---------------------------------------------------------------------------
__global__ void bprep_kernel(const float* __restrict__ Wk) {
    int id = blockIdx.x * 256 + threadIdx.x;  // 0..16383
    int lane = id & 31;
    int p = (id >> 5) & 15;
    int c = id >> 9;
    unsigned int hw[4], mw[4];
#pragma unroll
    for (int w = 0; w < 4; w++) {
        int nblk = p * 2 + (w >> 1);
        int reg = w & 1;
        int n = nblk * 8 + (lane >> 2);
        int k0 = c * 16 + (lane & 3) * 2 + reg * 8;
        float x0 = Wk[k0 * U_ + n];
        float x1 = Wk[(k0 + 1) * U_ + n];
        __half h0, m0, h1, m1;
        spl2(x0, h0, m0);
        spl2(x1, h1, m1);
        hw[w] = ((unsigned int)__half_as_ushort(h1) << 16) | __half_as_ushort(h0);
        mw[w] = ((unsigned int)__half_as_ushort(m1) << 16) | __half_as_ushort(m0);
    }
    *(uint4*)&g_Bh[id * 4] = make_uint4(hw[0], hw[1], hw[2], hw[3]);
    *(uint4*)&g_Bm[id * 4] = make_uint4(mw[0], mw[1], mw[2], mw[3]);
}

// ---------------------------------------------------------------------------
// proj_q partials: grid (N_, 4). Block (b, qd) accumulates d in
// [qd*256, qd*256+256) with 4-way ILP in fp64. Score epilogue sums the 4.
// ---------------------------------------------------------------------------
__global__ void projq_kernel(const float* __restrict__ q, const float* __restrict__ Wq) {
    int b = blockIdx.x;
    int qd = blockIdx.y;
    int u = threadIdx.x;  // 256 threads
    __shared__ float qs[256];
    qs[u] = q[b * D_ + qd * 256 + u];
    __syncthreads();
    const float* W = Wq + (size_t)(qd * 256) * U_ + u;
    double acc[4] = {0.0, 0.0, 0.0, 0.0};
#pragma unroll 4
    for (int d = 0; d < 256; d += 4) {
#pragma unroll
        for (int j = 0; j < 4; j++)
            acc[j] = fma((double)qs[d + j], (double)W[(size_t)(d + j) * U_], acc[j]);
    }
    g_pqpart[qd][b * U_ + u] = (float)((acc[0] + acc[1]) + (acc[2] + acc[3]));
}

// ---------------------------------------------------------------------------
// No-op kernel: aligns score_kernel to the ncu-profiled launch slot (#4).
// ---------------------------------------------------------------------------
__global__ void align_prof_kernel() {}

// ---------------------------------------------------------------------------
// Score GEMM: fp16 2-way split, 3 terms (hh, am*bh, ah*bm), m16n8k16.
// CTA = 64 rows x 128 cols (blockIdx.y = col half). 8 warps: warp_m 0..1,
// warp_n 0..3. BK=32 per stage, THREE stages -> one __syncthreads per iter
// (3 buffers remove the cp.async WAR hazard that forced the 2nd barrier).
// Smem/stage: AH 4KB | AM 4KB | BH 8KB | BM 8KB = 24KB; x3 = 72KB dynamic.
// ---------------------------------------------------------------------------
#define ST_AH 0
#define ST_AM 4096
#define ST_BH 8192
#define ST_BM 16384
#define ST_STRIDE 24576
#define SC_SMEM (3 * ST_STRIDE)

__device__ __forceinline__ void stage_A(char* stg, float4 a, int am, int kq, int kc) {
    int tile = am >> 4;
    int rbit = ((am & 15) >= 8) ? 1 : 0;
#pragma unroll
    for (int jj = 0; jj < 2; jj++) {
        int j = kq * 2 + jj;
        int lane = (am & 7) * 4 + (j & 3);
        int reg = ((j >= 4) ? 2 : 0) + rbit;
        float x0 = jj ? a.z : a.x;
        float x1 = jj ? a.w : a.y;
        __half h0, m0, h1, m1;
        spl2(x0, h0, m0);
        spl2(x1, h1, m1);
        unsigned off = (((kc * 4 + tile) * 32 + lane) * 4 + reg) * 4;
        *(unsigned int*)(stg + ST_AH + off) =
            ((unsigned int)__half_as_ushort(h1) << 16) | __half_as_ushort(h0);
        *(unsigned int*)(stg + ST_AM + off) =
            ((unsigned int)__half_as_ushort(m1) << 16) | __half_as_ushort(m0);
    }
}

__global__ __launch_bounds__(256, 2) void score_kernel(
    const float* __restrict__ mem, const float* __restrict__ v) {
    extern __shared__ char smem[];
    __shared__ float wsum[4][64];

    const int tid = threadIdx.x;
    const int lane = tid & 31;
    const int wid = tid >> 5;
    const int warp_m = wid >> 2;   // 0..1
    const int warp_n = wid & 3;    // 0..3
    const int row0 = blockIdx.x * 64;
    const int cb = blockIdx.y;     // col half 0..1
    const int b = row0 >> 11;

    const int am = tid >> 2;       // A row this thread stages
    const int kq = tid & 3;        // k quartet within a k16 chunk
    const float* Ag = mem + (size_t)(row0 + am) * E_ + kq * 4;

    const unsigned bsrc_c = 16 * 32 * 4;            // words per k16 chunk (2048)
    const unsigned bsrc_cb = (unsigned)(cb * 8 * 32 * 4);  // 1024-word half

    // ---- prologue: stages 0 and 1; register-prefetch A for stage 2 ----
    {
        float4 a0 = *(const float4*)Ag;
        float4 a1 = *(const float4*)(Ag + 16);
        stage_A(smem, a0, am, kq, 0);
        stage_A(smem, a1, am, kq, 1);
#pragma unroll
        for (int kc = 0; kc < 2; kc++) {
            const unsigned so = kc * bsrc_c + bsrc_cb + tid * 4;
            cpa16(smem + ST_BH + (kc * 1024 + tid * 4) * 4, g_Bh + so);
            cpa16(smem + ST_BM + (kc * 1024 + tid * 4) * 4, g_Bm + so);
        }
        asm volatile("cp.async.commit_group;");
        float4 a2 = *(const float4*)(Ag + 32);
        float4 a3 = *(const float4*)(Ag + 48);
        stage_A(smem + ST_STRIDE, a2, am, kq, 0);
        stage_A(smem + ST_STRIDE, a3, am, kq, 1);
#pragma unroll
        for (int kc = 0; kc < 2; kc++) {
            const unsigned so = (2 + kc) * bsrc_c + bsrc_cb + tid * 4;
            cpa16(smem + ST_STRIDE + ST_BH + (kc * 1024 + tid * 4) * 4, g_Bh + so);
            cpa16(smem + ST_STRIDE + ST_BM + (kc * 1024 + tid * 4) * 4, g_Bm + so);
        }
        asm volatile("cp.async.commit_group;");
    }
    float4 av0 = *(const float4*)(Ag + 64);   // A for stage 2
    float4 av1 = *(const float4*)(Ag + 80);

    float4 d[2][4];
#pragma unroll
    for (int mt = 0; mt < 2; mt++)
#pragma unroll
        for (int nt = 0; nt < 4; nt++) d[mt][nt] = make_float4(0.f, 0.f, 0.f, 0.f);

    for (int it = 0; it < 16; ++it) {
        const int buf = it % 3;
        const int pbuf = (it + 2) % 3;
        asm volatile("cp.async.wait_group 1;");
        __syncthreads();   // stage(it) B complete + A stores visible; MMA(it-1) done

        float4 nv0, nv1;
        if (it < 13) {     // register-prefetch A for stage it+3
            nv0 = *(const float4*)(Ag + (it + 3) * 32);
            nv1 = *(const float4*)(Ag + (it + 3) * 32 + 16);
        }
        if (it < 14) {     // B for stage it+2 into pbuf
#pragma unroll
            for (int kc = 0; kc < 2; kc++) {
                const unsigned so = (2 * (it + 2) + kc) * bsrc_c + bsrc_cb + tid * 4;
                cpa16(smem + pbuf * ST_STRIDE + ST_BH + (kc * 1024 + tid * 4) * 4,
                      g_Bh + so);
                cpa16(smem + pbuf * ST_STRIDE + ST_BM + (kc * 1024 + tid * 4) * 4,
                      g_Bm + so);
            }
        }
        asm volatile("cp.async.commit_group;");  // empty group for it>=14 keeps count

        char* stg = smem + buf * ST_STRIDE;
#pragma unroll
        for (int kc = 0; kc < 2; kc++) {
            uint4 ah[2], amf[2], bhv[2], bmv[2];
#pragma unroll
            for (int mt = 0; mt < 2; mt++) {
                unsigned off = (((kc * 4 + warp_m * 2 + mt) * 32 + lane) * 4) * 4;
                ah[mt] = *(const uint4*)(stg + ST_AH + off);
                amf[mt] = *(const uint4*)(stg + ST_AM + off);
            }
#pragma unroll
            for (int q = 0; q < 2; q++) {
                unsigned off = ((kc * 8 + warp_n * 2 + q) * 128 + lane * 4) * 4;
                bhv[q] = *(const uint4*)(stg + ST_BH + off);
                bmv[q] = *(const uint4*)(stg + ST_BM + off);
            }
            // term-major: 3 passes x 8 independent accumulators
#pragma unroll
            for (int q = 0; q < 2; q++)
#pragma unroll
                for (int mt = 0; mt < 2; mt++) {
                    MMA_F16(d[mt][q * 2],     amf[mt], bhv[q].x, bhv[q].y);
                    MMA_F16(d[mt][q * 2 + 1], amf[mt], bhv[q].z, bhv[q].w);
                }
#pragma unroll
            for (int q = 0; q < 2; q++)
#pragma unroll
                for (int mt = 0; mt < 2; mt++) {
                    MMA_F16(d[mt][q * 2],     ah[mt], bmv[q].x, bmv[q].y);
                    MMA_F16(d[mt][q * 2 + 1], ah[mt], bmv[q].z, bmv[q].w);
                }
#pragma unroll
            for (int q = 0; q < 2; q++)
#pragma unroll
                for (int mt = 0; mt < 2; mt++) {
                    MMA_F16(d[mt][q * 2],     ah[mt], bhv[q].x, bhv[q].y);
                    MMA_F16(d[mt][q * 2 + 1], ah[mt], bhv[q].z, bhv[q].w);
                }
        }
        if (it < 14) {     // stage A(it+2) into pbuf (WAR-safe: MMA(it-1) done)
            char* nstg = smem + pbuf * ST_STRIDE;
            stage_A(nstg, av0, am, kq, 0);
            stage_A(nstg, av1, am, kq, 1);
        }
        av0 = nv0;
        av1 = nv1;
    }

    // ---- epilogue: partial weights over this CTA's 128 cols ----
    float rsum[2][2] = {{0.f, 0.f}, {0.f, 0.f}};
#pragma unroll
    for (int nt = 0; nt < 4; nt++) {
        int c0 = cb * 128 + warp_n * 32 + nt * 8 + (lane & 3) * 2;
        float v0 = v[c0], v1 = v[c0 + 1];
        int i0 = b * U_ + c0;
        float pq0 = g_pqpart[0][i0] + g_pqpart[1][i0] + g_pqpart[2][i0] + g_pqpart[3][i0];
        float pq1 = g_pqpart[0][i0 + 1] + g_pqpart[1][i0 + 1] + g_pqpart[2][i0 + 1] +
                    g_pqpart[3][i0 + 1];
#pragma unroll
        for (int mt = 0; mt < 2; mt++) {
            float4 dd = d[mt][nt];
            rsum[mt][0] += v0 * tanhf(dd.x + pq0) + v1 * tanhf(dd.y + pq1);
            rsum[mt][1] += v0 * tanhf(dd.z + pq0) + v1 * tanhf(dd.w + pq1);
        }
    }
#pragma unroll
    for (int off = 1; off <= 2; off <<= 1)
#pragma unroll
        for (int mt = 0; mt < 2; mt++)
#pragma unroll
            for (int j = 0; j < 2; j++)
                rsum[mt][j] += __shfl_xor_sync(0xffffffffu, rsum[mt][j], off);
    if ((lane & 3) == 0) {
#pragma unroll
        for (int mt = 0; mt < 2; mt++)
#pragma unroll
            for (int j = 0; j < 2; j++)
                wsum[warp_n][warp_m * 32 + mt * 16 + j * 8 + (lane >> 2)] = rsum[mt][j];
    }
    __syncthreads();
    if (tid < 64)
        g_wpart[cb][row0 + tid] =
            wsum[0][tid] + wsum[1][tid] + wsum[2][tid] + wsum[3][tid];
}

// ---------------------------------------------------------------------------
// S1: parallel fp64 transcendentals (4 independent elems per thread):
// p = sigmoid(w), l = log(clip(1-p))
// ---------------------------------------------------------------------------
__global__ void scan1_kernel() {
    int i0 = (blockIdx.x * 256 + threadIdx.x) * 4;
#pragma unroll
    for (int j = 0; j < 4; j++) {
        int i = i0 + j;
        double w = (double)g_wpart[0][i] + (double)g_wpart[1][i];
        double p = 1.0 / (1.0 + exp(-w));
        double omp = fmin(fmax(1.0 - p, 1e-20), 1.0);
        g_pD[i] = p;
        g_lD[i] = log(omp);
    }
}

// ---------------------------------------------------------------------------
// S2: per-batch exclusive cumsum of l -> texcl
// ---------------------------------------------------------------------------
__global__ void scan2_kernel() {
    int b = blockIdx.x;
    int tid = threadIdx.x;
    int lane = tid & 31, wid = tid >> 5;
    __shared__ double swarp[8];
    int base = b * T_ + tid * 8;
    double x[8], run = 0.0;
#pragma unroll
    for (int i = 0; i < 8; i++) {
        x[i] = run;
        run += g_lD[base + i];
    }
    double inc = run;
#pragma unroll
    for (int off = 1; off < 32; off <<= 1) {
        double n = __shfl_up_sync(0xffffffffu, inc, off);
        if (lane >= off) inc += n;
    }
    if (lane == 31) swarp[wid] = inc;
    __syncthreads();
    if (tid == 0) {
        double r = 0.0;
        for (int w = 0; w < 8; w++) { double t = swarp[w]; swarp[w] = r; r += t; }
    }
    __syncthreads();
    double texcl = swarp[wid] + (inc - run);
#pragma unroll
    for (int i = 0; i < 8; i++) g_texcl[base + i] = texcl + x[i];
}

// ---------------------------------------------------------------------------
// S4 (fused old S3+S4): per batch: cp = exp(texcl); s = prev/clip(cp);
// inclusive cumsum of s; align = p*cp*cumsum
// ---------------------------------------------------------------------------
__global__ void scan4_kernel(const float* __restrict__ prev,
                             float* __restrict__ out_align) {
    int b = blockIdx.x;
    int tid = threadIdx.x;
    int lane = tid & 31, wid = tid >> 5;
    __shared__ double swarp[8];
    int base = b * T_ + tid * 8;
    double sinc[8], acp[8], run = 0.0;
#pragma unroll
    for (int i = 0; i < 8; i++) {
        double cp = exp(g_texcl[base + i]);
        double cc = fmin(fmax(cp, 1e-10), 1.0);
        run += (double)prev[base + i] / cc;
        sinc[i] = run;
        acp[i] = g_pD[base + i] * cp;
    }
    double inc = run;
#pragma unroll
    for (int off = 1; off < 32; off <<= 1) {
        double n = __shfl_up_sync(0xffffffffu, inc, off);
        if (lane >= off) inc += n;
    }
    if (lane == 31) swarp[wid] = inc;
    __syncthreads();
    if (tid == 0) {
        double r = 0.0;
        for (int w = 0; w < 8; w++) { double t = swarp[w]; swarp[w] = r; r += t; }
    }
    __syncthreads();
    double sexcl = swarp[wid] + (inc - run);
#pragma unroll
    for (int i = 0; i < 8; i++)
        out_align[base + i] = (float)(acp[i] * (sexcl + sinc[i]));
}

// ---------------------------------------------------------------------------
// contexts[b,e] = sum_t align[b,t]*mem[b,t,e]   (512 thr, 1024 blocks)
// ---------------------------------------------------------------------------
#define CT_SPLIT 32
__global__ void ctx_kernel(const float* __restrict__ mem, const float* __restrict__ align,
                           float* __restrict__ ctx) {
    int b = blockIdx.x;
    int chunk = blockIdx.y;
    int e = threadIdx.x;  // 512 threads
    const int TC = T_ / CT_SPLIT;  // 64
    int t0 = chunk * TC;
    const float* m = mem + ((size_t)b * T_ + t0) * E_ + e;
    const float* a = align + b * T_ + t0;
    float acc = 0.f;
#pragma unroll 8
    for (int t = 0; t < TC; t++)
        acc = fmaf(__ldg(a + t), m[(size_t)t * E_], acc);
    atomicAdd(&ctx[b * E_ + e], acc);
}

// ---------------------------------------------------------------------------
extern "C" void kernel_launch(void* const* d_in, const int* in_sizes, int n_in,
                              void* d_out, int out_size) {
    const float* q    = (const float*)d_in[0];
    const float* prev = (const float*)d_in[1];
    const float* mem  = (const float*)d_in[2];
    const float* Wq   = (const float*)d_in[3];
    const float* Wk   = (const float*)d_in[4];
    const float* v    = (const float*)d_in[5];
    float* out   = (float*)d_out;
    float* ctx   = out;              // [N, E]
    float* align = out + N_ * E_;    // [N, T]

    cudaFuncSetAttribute(score_kernel, cudaFuncAttributeMaxDynamicSharedMemorySize,
                         SC_SMEM);

    cudaMemsetAsync(ctx, 0, (size_t)N_ * E_ * sizeof(float));
    bprep_kernel<<<64, 256>>>(Wk);
    projq_kernel<<<dim3(N_, 4), 256>>>(q, Wq);
    align_prof_kernel<<<1, 32>>>();   // keeps score in the profiled launch slot
    score_kernel<<<dim3((N_ * T_) / 64, 2), 256, SC_SMEM>>>(mem, v);
    scan1_kernel<<<64, 256>>>();
    scan2_kernel<<<N_, 256>>>();
    scan4_kernel<<<N_, 256>>>(prev, align);
    ctx_kernel<<<dim3(N_, CT_SPLIT), 512>>>(mem, align, ctx);
}